// round 1
// baseline (speedup 1.0000x reference)
#include <cuda_runtime.h>
#include <math.h>

#define MTOK  16384
#define CDIM  768
#define TSEQ  1024
#define BATCH 16
#define NHEAD 8
#define HDIM  96

// ---------------- scratch (no allocation allowed) ----------------
__device__ float g_h  [(size_t)MTOK * CDIM];        // ln output
__device__ float g_qkv[(size_t)MTOK * 3 * CDIM];    // qkv
__device__ float g_y  [(size_t)MTOK * CDIM];        // attn output
__device__ float g_x1 [(size_t)MTOK * CDIM];        // post-attn residual
__device__ float g_h2 [(size_t)MTOK * 4 * CDIM];    // gelu(fc) activations

// ---------------- layernorm ----------------
__global__ __launch_bounds__(256) void ln_kernel(
    const float* __restrict__ x, const float* __restrict__ g,
    const float* __restrict__ b, float* __restrict__ out)
{
    const int row = blockIdx.x;
    const int tid = threadIdx.x;
    const float* xr = x + (size_t)row * CDIM;
    float vals[3];
    float s = 0.f, s2 = 0.f;
#pragma unroll
    for (int j = 0; j < 3; j++) {
        float t = xr[tid + 256 * j];
        vals[j] = t; s += t; s2 += t * t;
    }
#pragma unroll
    for (int o = 16; o > 0; o >>= 1) {
        s  += __shfl_xor_sync(0xffffffffu, s,  o);
        s2 += __shfl_xor_sync(0xffffffffu, s2, o);
    }
    __shared__ float rs[8], rs2[8];
    const int wid = tid >> 5, lane = tid & 31;
    if (lane == 0) { rs[wid] = s; rs2[wid] = s2; }
    __syncthreads();
    s = 0.f; s2 = 0.f;
#pragma unroll
    for (int w = 0; w < 8; w++) { s += rs[w]; s2 += rs2[w]; }
    const float mu  = s * (1.0f / CDIM);
    const float var = s2 * (1.0f / CDIM) - mu * mu;
    const float rstd = rsqrtf(var + 1e-5f);
    float* orow = out + (size_t)row * CDIM;
#pragma unroll
    for (int j = 0; j < 3; j++) {
        const int c = tid + 256 * j;
        orow[c] = (vals[j] - mu) * rstd * g[c] + b[c];
    }
}

// ---------------- SGEMM 128x128x16, 8x8 micro-tile ----------------
__device__ __forceinline__ float gelu_f(float x) {
    const float x3 = x * x * x;
    return 0.5f * x * (1.0f + tanhf(0.7978845608028654f * (x + 0.044715f * x3)));
}

// EPI: 0 = bias, 1 = bias+residual, 2 = bias+gelu
template <int EPI>
__global__ __launch_bounds__(256) void sgemm_kernel(
    const float* __restrict__ A, const float* __restrict__ B,
    const float* __restrict__ bias, const float* __restrict__ res,
    float* __restrict__ C, int N, int K)
{
    __shared__ float As[16][132];   // transposed, padded (528B rows, 16B aligned)
    __shared__ float Bs[16][128];

    const int tid = threadIdx.x;
    const int tx = tid & 15, ty = tid >> 4;
    const int bx = blockIdx.x, by = blockIdx.y;

    const int ar = tid >> 2;            // + 64*t
    const int ak = (tid & 3) * 4;
    const int br = tid >> 5;            // + 8*t
    const int bc = (tid & 31) * 4;

    const float* Ap = A + (size_t)(by * 128) * K;
    const float* Bp = B + bx * 128;

    float4 pa[2], pb[2];
    float acc[8][8];
#pragma unroll
    for (int i = 0; i < 8; i++)
#pragma unroll
        for (int j = 0; j < 8; j++) acc[i][j] = 0.f;

#pragma unroll
    for (int t = 0; t < 2; t++) {
        pa[t] = *(const float4*)(Ap + (size_t)(ar + 64 * t) * K + ak);
        pb[t] = *(const float4*)(Bp + (size_t)(br + 8 * t) * N + bc);
    }

    const int nk = K >> 4;
    for (int kt = 0; kt < nk; ++kt) {
#pragma unroll
        for (int t = 0; t < 2; t++) {
            As[ak + 0][ar + 64 * t] = pa[t].x;
            As[ak + 1][ar + 64 * t] = pa[t].y;
            As[ak + 2][ar + 64 * t] = pa[t].z;
            As[ak + 3][ar + 64 * t] = pa[t].w;
            *(float4*)&Bs[br + 8 * t][bc] = pb[t];
        }
        __syncthreads();
        if (kt + 1 < nk) {
            const float* An = Ap + (kt + 1) * 16;
            const float* Bn = Bp + (size_t)(kt + 1) * 16 * N;
#pragma unroll
            for (int t = 0; t < 2; t++) {
                pa[t] = *(const float4*)(An + (size_t)(ar + 64 * t) * K + ak);
                pb[t] = *(const float4*)(Bn + (size_t)(br + 8 * t) * N + bc);
            }
        }
#pragma unroll
        for (int k = 0; k < 16; k++) {
            float4 a0 = *(const float4*)&As[k][ty * 8];
            float4 a1 = *(const float4*)&As[k][ty * 8 + 4];
            float4 b0 = *(const float4*)&Bs[k][tx * 8];
            float4 b1 = *(const float4*)&Bs[k][tx * 8 + 4];
            float af[8] = {a0.x, a0.y, a0.z, a0.w, a1.x, a1.y, a1.z, a1.w};
            float bf[8] = {b0.x, b0.y, b0.z, b0.w, b1.x, b1.y, b1.z, b1.w};
#pragma unroll
            for (int i = 0; i < 8; i++)
#pragma unroll
                for (int j = 0; j < 8; j++)
                    acc[i][j] = fmaf(af[i], bf[j], acc[i][j]);
        }
        __syncthreads();
    }

    const int row0 = by * 128 + ty * 8;
    const int col0 = bx * 128 + tx * 8;
    float bv[8];
#pragma unroll
    for (int j = 0; j < 8; j++) bv[j] = bias[col0 + j];
#pragma unroll
    for (int i = 0; i < 8; i++) {
        const size_t base = (size_t)(row0 + i) * N + col0;
#pragma unroll
        for (int p = 0; p < 2; p++) {
            float4 v;
            v.x = acc[i][p * 4 + 0] + bv[p * 4 + 0];
            v.y = acc[i][p * 4 + 1] + bv[p * 4 + 1];
            v.z = acc[i][p * 4 + 2] + bv[p * 4 + 2];
            v.w = acc[i][p * 4 + 3] + bv[p * 4 + 3];
            if (EPI == 1) {
                float4 r = *(const float4*)(res + base + p * 4);
                v.x += r.x; v.y += r.y; v.z += r.z; v.w += r.w;
            } else if (EPI == 2) {
                v.x = gelu_f(v.x); v.y = gelu_f(v.y);
                v.z = gelu_f(v.z); v.w = gelu_f(v.w);
            }
            *(float4*)(C + base + p * 4) = v;
        }
    }
}

// ---------------- flash attention (causal, fp32) ----------------
// grid (T/64, H, B), 64 threads; thread = one query row.
__global__ __launch_bounds__(64) void attn_kernel(
    const float* __restrict__ qkv, float* __restrict__ y)
{
    const int qt = blockIdx.x, h = blockIdx.y, b = blockIdx.z;
    const int tid = threadIdx.x;
    const int q0 = qt * 64;
    const int r = q0 + tid;

    __shared__ float q_s[64][100];   // padded: stride 25 float4 -> conflict-free
    __shared__ float k_s[16][96];
    __shared__ float v_s[16][96];

    // cooperative Q tile load: 64 rows x 24 float4
#pragma unroll
    for (int i = 0; i < 24; i++) {
        const int id = i * 64 + tid;
        const int row = id / 24, c = id % 24;
        float4 qv = *(const float4*)(qkv + (size_t)(b * TSEQ + q0 + row) * 2304 + h * 96 + c * 4);
        *(float4*)&q_s[row][c * 4] = qv;
    }

    float4 o4[24];
#pragma unroll
    for (int c = 0; c < 24; c++) o4[c] = make_float4(0.f, 0.f, 0.f, 0.f);
    float m = -1e30f, l = 0.f;
    const float scale = 0.10206207261596575f;   // 1/sqrt(96)

    const int nchunks = 4 * qt + 4;             // keys 0 .. q0+63 in chunks of 16
    for (int jc = 0; jc < nchunks; ++jc) {
        __syncthreads();                        // protect k_s/v_s reuse (& Q visibility 1st iter)
        const int kb = jc * 16;
#pragma unroll
        for (int i = 0; i < 6; i++) {
            const int id = i * 64 + tid;        // 0..383 over 16 rows x 24 float4
            const int row = id / 24, c = id % 24;
            const float* base = qkv + (size_t)(b * TSEQ + kb + row) * 2304 + h * 96 + c * 4;
            *(float4*)&k_s[row][c * 4] = *(const float4*)(base + 768);
            *(float4*)&v_s[row][c * 4] = *(const float4*)(base + 1536);
        }
        __syncthreads();

        float s[16];
#pragma unroll
        for (int j = 0; j < 16; j++) s[j] = 0.f;
#pragma unroll
        for (int c4 = 0; c4 < 24; c4++) {
            float4 q4 = *(const float4*)&q_s[tid][c4 * 4];
#pragma unroll
            for (int j = 0; j < 16; j++) {
                float4 k4 = *(const float4*)&k_s[j][c4 * 4];
                s[j] = fmaf(q4.x, k4.x, fmaf(q4.y, k4.y,
                       fmaf(q4.z, k4.z, fmaf(q4.w, k4.w, s[j]))));
            }
        }

        float mn = m;
#pragma unroll
        for (int j = 0; j < 16; j++) {
            const float sv = (kb + j <= r) ? s[j] * scale : -1e30f;
            s[j] = sv;
            mn = fmaxf(mn, sv);
        }
        const float f = __expf(m - mn);
        m = mn;
        float ls = 0.f;
#pragma unroll
        for (int j = 0; j < 16; j++) {
            const float p = __expf(s[j] - m);
            s[j] = p; ls += p;
        }
        l = l * f + ls;
#pragma unroll
        for (int c = 0; c < 24; c++) {
            o4[c].x *= f; o4[c].y *= f; o4[c].z *= f; o4[c].w *= f;
        }
#pragma unroll
        for (int j = 0; j < 16; j++) {
            const float p = s[j];
#pragma unroll
            for (int c = 0; c < 24; c++) {
                float4 v4 = *(const float4*)&v_s[j][c * 4];
                o4[c].x = fmaf(p, v4.x, o4[c].x);
                o4[c].y = fmaf(p, v4.y, o4[c].y);
                o4[c].z = fmaf(p, v4.z, o4[c].z);
                o4[c].w = fmaf(p, v4.w, o4[c].w);
            }
        }
    }

    const float inv = 1.0f / l;
    float* yr = y + (size_t)(b * TSEQ + r) * 768 + h * 96;
#pragma unroll
    for (int c = 0; c < 24; c++) {
        float4 v = o4[c];
        v.x *= inv; v.y *= inv; v.z *= inv; v.w *= inv;
        *(float4*)(yr + c * 4) = v;
    }
}

// ---------------- launch ----------------
extern "C" void kernel_launch(void* const* d_in, const int* in_sizes, int n_in,
                              void* d_out, int out_size)
{
    const float* x      = (const float*)d_in[0];
    const float* ln1_g  = (const float*)d_in[1];
    const float* ln1_b  = (const float*)d_in[2];
    const float* attn_w = (const float*)d_in[3];
    const float* attn_b = (const float*)d_in[4];
    const float* proj_w = (const float*)d_in[5];
    const float* proj_b = (const float*)d_in[6];
    const float* ln2_g  = (const float*)d_in[7];
    const float* ln2_b  = (const float*)d_in[8];
    const float* fc_w   = (const float*)d_in[9];
    const float* fc_b   = (const float*)d_in[10];
    const float* fc2_w  = (const float*)d_in[11];
    const float* fc2_b  = (const float*)d_in[12];
    float* out = (float*)d_out;

    float *h, *qkv, *y, *x1, *h2;
    cudaGetSymbolAddress((void**)&h,   g_h);
    cudaGetSymbolAddress((void**)&qkv, g_qkv);
    cudaGetSymbolAddress((void**)&y,   g_y);
    cudaGetSymbolAddress((void**)&x1,  g_x1);
    cudaGetSymbolAddress((void**)&h2,  g_h2);

    // 1) h = ln1(x)
    ln_kernel<<<MTOK, 256>>>(x, ln1_g, ln1_b, h);
    // 2) qkv = h @ attn_w + attn_b       [16384,768]x[768,2304]
    sgemm_kernel<0><<<dim3(2304 / 128, MTOK / 128), 256>>>(h, attn_w, attn_b, nullptr, qkv, 2304, 768);
    // 3) y = causal MHA(qkv)
    attn_kernel<<<dim3(TSEQ / 64, NHEAD, BATCH), 64>>>(qkv, y);
    // 4) x1 = x + y @ proj_w + proj_b    [16384,768]x[768,768]
    sgemm_kernel<1><<<dim3(768 / 128, MTOK / 128), 256>>>(y, proj_w, proj_b, x, x1, 768, 768);
    // 5) h = ln2(x1)
    ln_kernel<<<MTOK, 256>>>(x1, ln2_g, ln2_b, h);
    // 6) h2 = gelu(h @ fc_w + fc_b)      [16384,768]x[768,3072]
    sgemm_kernel<2><<<dim3(3072 / 128, MTOK / 128), 256>>>(h, fc_w, fc_b, nullptr, h2, 3072, 768);
    // 7) out = x1 + h2 @ fc2_w + fc2_b   [16384,3072]x[3072,768]
    sgemm_kernel<1><<<dim3(768 / 128, MTOK / 128), 256>>>(h2, fc2_w, fc2_b, x1, out, 768, 3072);
}

// round 2
// speedup vs baseline: 1.1736x; 1.1736x over previous
#include <cuda_runtime.h>
#include <math.h>
#include <mma.h>

using namespace nvcuda;

#define MTOK  16384
#define CDIM  768
#define TSEQ  1024
#define BATCH 16
#define NHEAD 8
#define HDIM  96

// ---------------- scratch (no allocation allowed) ----------------
__device__ float g_h  [(size_t)MTOK * CDIM];        // ln output
__device__ float g_qkv[(size_t)MTOK * 3 * CDIM];    // qkv
__device__ float g_y  [(size_t)MTOK * CDIM];        // attn output
__device__ float g_x1 [(size_t)MTOK * CDIM];        // post-attn residual
__device__ float g_h2 [(size_t)MTOK * 4 * CDIM];    // gelu(fc) activations

// ---------------- layernorm ----------------
__global__ __launch_bounds__(256) void ln_kernel(
    const float* __restrict__ x, const float* __restrict__ g,
    const float* __restrict__ b, float* __restrict__ out)
{
    const int row = blockIdx.x;
    const int tid = threadIdx.x;
    const float* xr = x + (size_t)row * CDIM;
    float vals[3];
    float s = 0.f, s2 = 0.f;
#pragma unroll
    for (int j = 0; j < 3; j++) {
        float t = xr[tid + 256 * j];
        vals[j] = t; s += t; s2 += t * t;
    }
#pragma unroll
    for (int o = 16; o > 0; o >>= 1) {
        s  += __shfl_xor_sync(0xffffffffu, s,  o);
        s2 += __shfl_xor_sync(0xffffffffu, s2, o);
    }
    __shared__ float rs[8], rs2[8];
    const int wid = tid >> 5, lane = tid & 31;
    if (lane == 0) { rs[wid] = s; rs2[wid] = s2; }
    __syncthreads();
    s = 0.f; s2 = 0.f;
#pragma unroll
    for (int w = 0; w < 8; w++) { s += rs[w]; s2 += rs2[w]; }
    const float mu  = s * (1.0f / CDIM);
    const float var = s2 * (1.0f / CDIM) - mu * mu;
    const float rstd = rsqrtf(var + 1e-5f);
    float* orow = out + (size_t)row * CDIM;
#pragma unroll
    for (int j = 0; j < 3; j++) {
        const int c = tid + 256 * j;
        orow[c] = (vals[j] - mu) * rstd * g[c] + b[c];
    }
}

// ---------------- TF32 tensor-core GEMM 128x128x32 ----------------
__device__ __forceinline__ float gelu_f(float x) {
    const float x3 = x * x * x;
    return 0.5f * x * (1.0f + tanhf(0.7978845608028654f * (x + 0.044715f * x3)));
}

// EPI: 0 = bias, 1 = bias+residual, 2 = bias+gelu
template <int EPI>
__global__ __launch_bounds__(256) void tgemm_kernel(
    const float* __restrict__ A, const float* __restrict__ B,
    const float* __restrict__ bias, const float* __restrict__ res,
    float* __restrict__ C, int N, int K)
{
    __shared__ float As[128][36];    // [m][k], pad 4 (row = 144B, 16B-aligned)
    __shared__ float Bs[32][132];    // [k][n], pad 4 (row = 528B, 16B-aligned)
    __shared__ float stg[8][16][16]; // per-warp epilogue staging

    const int tid  = threadIdx.x;
    const int wid  = tid >> 5, lane = tid & 31;
    const int wm   = wid >> 2;       // 0..1  (m group of 64)
    const int wn   = wid & 3;        // 0..3  (n group of 32)
    const int bx   = blockIdx.x, by = blockIdx.y;

    wmma::fragment<wmma::accumulator, 16, 16, 8, float> c[4][2];
#pragma unroll
    for (int i = 0; i < 4; i++)
#pragma unroll
        for (int j = 0; j < 2; j++) wmma::fill_fragment(c[i][j], 0.0f);

    const float* Ap = A + (size_t)(by * 128) * K;
    const float* Bp = B + bx * 128;

    float4 pa[4], pb[4];
    // prefetch tile 0
#pragma unroll
    for (int it = 0; it < 4; it++) {
        const int ia = it * 256 + tid;
        pa[it] = *(const float4*)(Ap + (size_t)(ia >> 3) * K + (ia & 7) * 4);
        pb[it] = *(const float4*)(Bp + (size_t)(ia >> 5) * N + (ia & 31) * 4);
    }

    const int nk = K >> 5;
    for (int kt = 0; kt < nk; ++kt) {
        // store prefetched tile to smem, truncating to tf32 once here
#pragma unroll
        for (int it = 0; it < 4; it++) {
            const int ia = it * 256 + tid;
            float4 va = pa[it], vb = pb[it];
            va.x = wmma::__float_to_tf32(va.x); va.y = wmma::__float_to_tf32(va.y);
            va.z = wmma::__float_to_tf32(va.z); va.w = wmma::__float_to_tf32(va.w);
            vb.x = wmma::__float_to_tf32(vb.x); vb.y = wmma::__float_to_tf32(vb.y);
            vb.z = wmma::__float_to_tf32(vb.z); vb.w = wmma::__float_to_tf32(vb.w);
            *(float4*)&As[ia >> 3][(ia & 7) * 4]  = va;
            *(float4*)&Bs[ia >> 5][(ia & 31) * 4] = vb;
        }
        __syncthreads();

        if (kt + 1 < nk) {
            const float* An = Ap + (kt + 1) * 32;
            const float* Bn = Bp + (size_t)((kt + 1) * 32) * N;
#pragma unroll
            for (int it = 0; it < 4; it++) {
                const int ia = it * 256 + tid;
                pa[it] = *(const float4*)(An + (size_t)(ia >> 3) * K + (ia & 7) * 4);
                pb[it] = *(const float4*)(Bn + (size_t)(ia >> 5) * N + (ia & 31) * 4);
            }
        }

#pragma unroll
        for (int kk = 0; kk < 4; kk++) {
            wmma::fragment<wmma::matrix_a, 16, 16, 8, wmma::precision::tf32, wmma::row_major> a[4];
            wmma::fragment<wmma::matrix_b, 16, 16, 8, wmma::precision::tf32, wmma::row_major> b[2];
#pragma unroll
            for (int mi = 0; mi < 4; mi++)
                wmma::load_matrix_sync(a[mi], &As[wm * 64 + mi * 16][kk * 8], 36);
#pragma unroll
            for (int nj = 0; nj < 2; nj++)
                wmma::load_matrix_sync(b[nj], &Bs[kk * 8][wn * 32 + nj * 16], 132);
#pragma unroll
            for (int mi = 0; mi < 4; mi++)
#pragma unroll
                for (int nj = 0; nj < 2; nj++)
                    wmma::mma_sync(c[mi][nj], a[mi], b[nj], c[mi][nj]);
        }
        __syncthreads();
    }

    // ---- epilogue via per-warp staging ----
    const int r  = lane >> 1;
    const int cs = (lane & 1) * 8;
#pragma unroll
    for (int mi = 0; mi < 4; mi++) {
#pragma unroll
        for (int nj = 0; nj < 2; nj++) {
            wmma::store_matrix_sync(&stg[wid][0][0], c[mi][nj], 16, wmma::mem_row_major);
            __syncwarp();
            const int row = by * 128 + wm * 64 + mi * 16 + r;
            const int col = bx * 128 + wn * 32 + nj * 16 + cs;
            const size_t base = (size_t)row * N + col;
            float4 b0 = *(const float4*)(bias + col);
            float4 b1 = *(const float4*)(bias + col + 4);
            float v[8];
#pragma unroll
            for (int u = 0; u < 8; u++) v[u] = stg[wid][r][cs + u];
            v[0] += b0.x; v[1] += b0.y; v[2] += b0.z; v[3] += b0.w;
            v[4] += b1.x; v[5] += b1.y; v[6] += b1.z; v[7] += b1.w;
            if (EPI == 1) {
                float4 r0 = *(const float4*)(res + base);
                float4 r1 = *(const float4*)(res + base + 4);
                v[0] += r0.x; v[1] += r0.y; v[2] += r0.z; v[3] += r0.w;
                v[4] += r1.x; v[5] += r1.y; v[6] += r1.z; v[7] += r1.w;
            } else if (EPI == 2) {
#pragma unroll
                for (int u = 0; u < 8; u++) v[u] = gelu_f(v[u]);
            }
            *(float4*)(C + base)     = make_float4(v[0], v[1], v[2], v[3]);
            *(float4*)(C + base + 4) = make_float4(v[4], v[5], v[6], v[7]);
            __syncwarp();
        }
    }
}

// ---------------- flash attention (causal, fp32) ----------------
__global__ __launch_bounds__(64) void attn_kernel(
    const float* __restrict__ qkv, float* __restrict__ y)
{
    const int qt = blockIdx.x, h = blockIdx.y, b = blockIdx.z;
    const int tid = threadIdx.x;
    const int q0 = qt * 64;
    const int r = q0 + tid;

    __shared__ float q_s[64][100];
    __shared__ float k_s[16][96];
    __shared__ float v_s[16][96];

#pragma unroll
    for (int i = 0; i < 24; i++) {
        const int id = i * 64 + tid;
        const int row = id / 24, c = id % 24;
        float4 qv = *(const float4*)(qkv + (size_t)(b * TSEQ + q0 + row) * 2304 + h * 96 + c * 4);
        *(float4*)&q_s[row][c * 4] = qv;
    }

    float4 o4[24];
#pragma unroll
    for (int c = 0; c < 24; c++) o4[c] = make_float4(0.f, 0.f, 0.f, 0.f);
    float m = -1e30f, l = 0.f;
    const float scale = 0.10206207261596575f;

    const int nchunks = 4 * qt + 4;
    for (int jc = 0; jc < nchunks; ++jc) {
        __syncthreads();
        const int kb = jc * 16;
#pragma unroll
        for (int i = 0; i < 6; i++) {
            const int id = i * 64 + tid;
            const int row = id / 24, c = id % 24;
            const float* base = qkv + (size_t)(b * TSEQ + kb + row) * 2304 + h * 96 + c * 4;
            *(float4*)&k_s[row][c * 4] = *(const float4*)(base + 768);
            *(float4*)&v_s[row][c * 4] = *(const float4*)(base + 1536);
        }
        __syncthreads();

        float s[16];
#pragma unroll
        for (int j = 0; j < 16; j++) s[j] = 0.f;
#pragma unroll
        for (int c4 = 0; c4 < 24; c4++) {
            float4 q4 = *(const float4*)&q_s[tid][c4 * 4];
#pragma unroll
            for (int j = 0; j < 16; j++) {
                float4 k4 = *(const float4*)&k_s[j][c4 * 4];
                s[j] = fmaf(q4.x, k4.x, fmaf(q4.y, k4.y,
                       fmaf(q4.z, k4.z, fmaf(q4.w, k4.w, s[j]))));
            }
        }

        float mn = m;
#pragma unroll
        for (int j = 0; j < 16; j++) {
            const float sv = (kb + j <= r) ? s[j] * scale : -1e30f;
            s[j] = sv;
            mn = fmaxf(mn, sv);
        }
        const float f = __expf(m - mn);
        m = mn;
        float ls = 0.f;
#pragma unroll
        for (int j = 0; j < 16; j++) {
            const float p = __expf(s[j] - m);
            s[j] = p; ls += p;
        }
        l = l * f + ls;
#pragma unroll
        for (int c = 0; c < 24; c++) {
            o4[c].x *= f; o4[c].y *= f; o4[c].z *= f; o4[c].w *= f;
        }
#pragma unroll
        for (int j = 0; j < 16; j++) {
            const float p = s[j];
#pragma unroll
            for (int c = 0; c < 24; c++) {
                float4 v4 = *(const float4*)&v_s[j][c * 4];
                o4[c].x = fmaf(p, v4.x, o4[c].x);
                o4[c].y = fmaf(p, v4.y, o4[c].y);
                o4[c].z = fmaf(p, v4.z, o4[c].z);
                o4[c].w = fmaf(p, v4.w, o4[c].w);
            }
        }
    }

    const float inv = 1.0f / l;
    float* yr = y + (size_t)(b * TSEQ + r) * 768 + h * 96;
#pragma unroll
    for (int c = 0; c < 24; c++) {
        float4 v = o4[c];
        v.x *= inv; v.y *= inv; v.z *= inv; v.w *= inv;
        *(float4*)(yr + c * 4) = v;
    }
}

// ---------------- launch ----------------
extern "C" void kernel_launch(void* const* d_in, const int* in_sizes, int n_in,
                              void* d_out, int out_size)
{
    const float* x      = (const float*)d_in[0];
    const float* ln1_g  = (const float*)d_in[1];
    const float* ln1_b  = (const float*)d_in[2];
    const float* attn_w = (const float*)d_in[3];
    const float* attn_b = (const float*)d_in[4];
    const float* proj_w = (const float*)d_in[5];
    const float* proj_b = (const float*)d_in[6];
    const float* ln2_g  = (const float*)d_in[7];
    const float* ln2_b  = (const float*)d_in[8];
    const float* fc_w   = (const float*)d_in[9];
    const float* fc_b   = (const float*)d_in[10];
    const float* fc2_w  = (const float*)d_in[11];
    const float* fc2_b  = (const float*)d_in[12];
    float* out = (float*)d_out;

    float *h, *qkv, *y, *x1, *h2;
    cudaGetSymbolAddress((void**)&h,   g_h);
    cudaGetSymbolAddress((void**)&qkv, g_qkv);
    cudaGetSymbolAddress((void**)&y,   g_y);
    cudaGetSymbolAddress((void**)&x1,  g_x1);
    cudaGetSymbolAddress((void**)&h2,  g_h2);

    // 1) h = ln1(x)
    ln_kernel<<<MTOK, 256>>>(x, ln1_g, ln1_b, h);
    // 2) qkv = h @ attn_w + attn_b
    tgemm_kernel<0><<<dim3(2304 / 128, MTOK / 128), 256>>>(h, attn_w, attn_b, nullptr, qkv, 2304, 768);
    // 3) y = causal MHA(qkv)
    attn_kernel<<<dim3(TSEQ / 64, NHEAD, BATCH), 64>>>(qkv, y);
    // 4) x1 = x + y @ proj_w + proj_b
    tgemm_kernel<1><<<dim3(768 / 128, MTOK / 128), 256>>>(y, proj_w, proj_b, x, x1, 768, 768);
    // 5) h = ln2(x1)
    ln_kernel<<<MTOK, 256>>>(x1, ln2_g, ln2_b, h);
    // 6) h2 = gelu(h @ fc_w + fc_b)
    tgemm_kernel<2><<<dim3(3072 / 128, MTOK / 128), 256>>>(h, fc_w, fc_b, nullptr, h2, 3072, 768);
    // 7) out = x1 + h2 @ fc2_w + fc2_b
    tgemm_kernel<1><<<dim3(768 / 128, MTOK / 128), 256>>>(h2, fc2_w, fc2_b, x1, out, 768, 3072);
}

// round 3
// speedup vs baseline: 1.5681x; 1.3362x over previous
#include <cuda_runtime.h>
#include <math.h>
#include <mma.h>
#include <stdint.h>

using namespace nvcuda;

#define MTOK  16384
#define CDIM  768
#define TSEQ  1024
#define BATCH 16
#define NHEAD 8
#define HDIM  96

// ---------------- scratch (no allocation allowed) ----------------
__device__ float g_h  [(size_t)MTOK * CDIM];
__device__ float g_qkv[(size_t)MTOK * 3 * CDIM];
__device__ float g_y  [(size_t)MTOK * CDIM];
__device__ float g_x1 [(size_t)MTOK * CDIM];
__device__ float g_h2 [(size_t)MTOK * 4 * CDIM];

// ---------------- layernorm ----------------
__global__ __launch_bounds__(256) void ln_kernel(
    const float* __restrict__ x, const float* __restrict__ g,
    const float* __restrict__ b, float* __restrict__ out)
{
    const int row = blockIdx.x;
    const int tid = threadIdx.x;
    const float* xr = x + (size_t)row * CDIM;
    float vals[3];
    float s = 0.f, s2 = 0.f;
#pragma unroll
    for (int j = 0; j < 3; j++) {
        float t = xr[tid + 256 * j];
        vals[j] = t; s += t; s2 += t * t;
    }
#pragma unroll
    for (int o = 16; o > 0; o >>= 1) {
        s  += __shfl_xor_sync(0xffffffffu, s,  o);
        s2 += __shfl_xor_sync(0xffffffffu, s2, o);
    }
    __shared__ float rs[8], rs2[8];
    const int wid = tid >> 5, lane = tid & 31;
    if (lane == 0) { rs[wid] = s; rs2[wid] = s2; }
    __syncthreads();
    s = 0.f; s2 = 0.f;
#pragma unroll
    for (int w = 0; w < 8; w++) { s += rs[w]; s2 += rs2[w]; }
    const float mu  = s * (1.0f / CDIM);
    const float var = s2 * (1.0f / CDIM) - mu * mu;
    const float rstd = rsqrtf(var + 1e-5f);
    float* orow = out + (size_t)row * CDIM;
#pragma unroll
    for (int j = 0; j < 3; j++) {
        const int c = tid + 256 * j;
        orow[c] = (vals[j] - mu) * rstd * g[c] + b[c];
    }
}

// ---------------- TF32 tensor-core GEMM ----------------
// block 128x128, BK=16, 128 threads (4 warps 2x2), warp tile 64x64,
// cp.async double-buffered smem, one sync per k-tile, 2 CTAs/SM.
__device__ __forceinline__ float gelu_f(float x) {
    const float x3 = x * x * x;
    return 0.5f * x * (1.0f + tanhf(0.7978845608028654f * (x + 0.044715f * x3)));
}

__device__ __forceinline__ uint32_t smem_u32(const void* p) {
    return (uint32_t)__cvta_generic_to_shared(p);
}
__device__ __forceinline__ void cp16(uint32_t dst, const void* src) {
    asm volatile("cp.async.cg.shared.global [%0], [%1], 16;\n" :: "r"(dst), "l"(src));
}
#define CP_COMMIT() asm volatile("cp.async.commit_group;\n" ::: "memory")
#define CP_WAIT0()  asm volatile("cp.async.wait_group 0;\n" ::: "memory")

// EPI: 0 = bias, 1 = bias+residual, 2 = bias+gelu
template <int EPI>
__global__ __launch_bounds__(128) void tgemm_kernel(
    const float* __restrict__ A, const float* __restrict__ B,
    const float* __restrict__ bias, const float* __restrict__ res,
    float* __restrict__ C, int N, int K)
{
    __shared__ float As[2][128][20];   // [m][k], pad 4 (80B rows)
    __shared__ float Bs[2][16][132];   // [k][n], pad 4 (528B rows)
    __shared__ float stg[4][16][16];

    const int tid  = threadIdx.x;
    const int wid  = tid >> 5, lane = tid & 31;
    const int wm   = wid >> 1;       // 0..1
    const int wn   = wid & 1;        // 0..1
    const int bx   = blockIdx.x, by = blockIdx.y;

    wmma::fragment<wmma::accumulator, 16, 16, 8, float> c[4][4];
#pragma unroll
    for (int i = 0; i < 4; i++)
#pragma unroll
        for (int j = 0; j < 4; j++) wmma::fill_fragment(c[i][j], 0.0f);

    // per-thread copy assignments: 4 A float4 + 4 B float4 per tile
    const int a_row = tid >> 1;           // +64*it(0..1)? -> use idx scheme below
    // A: idx = it*128 + tid ; row = idx>>2, kq = (idx&3)*4
    // B: idx = it*128 + tid ; krow = idx>>5, col = (idx&31)*4
    const float* Agm = A + (size_t)(by * 128) * K;
    const float* Bgm = B + bx * 128;
    (void)a_row;

    const int nk = K >> 4;

    // prefetch tile 0 into buffer 0
#pragma unroll
    for (int it = 0; it < 4; it++) {
        const int idx = it * 128 + tid;
        const int ar = idx >> 2, ak = (idx & 3) * 4;
        const int bk = idx >> 5, bc = (idx & 31) * 4;
        cp16(smem_u32(&As[0][ar][ak]), Agm + (size_t)ar * K + ak);
        cp16(smem_u32(&Bs[0][bk][bc]), Bgm + (size_t)bk * N + bc);
    }
    CP_COMMIT();
    CP_WAIT0();
    __syncthreads();

    for (int kt = 0; kt < nk; ++kt) {
        const int buf = kt & 1;
        if (kt + 1 < nk) {
            const float* An = Agm + (kt + 1) * 16;
            const float* Bn = Bgm + (size_t)((kt + 1) * 16) * N;
#pragma unroll
            for (int it = 0; it < 4; it++) {
                const int idx = it * 128 + tid;
                const int ar = idx >> 2, ak = (idx & 3) * 4;
                const int bk = idx >> 5, bc = (idx & 31) * 4;
                cp16(smem_u32(&As[buf ^ 1][ar][ak]), An + (size_t)ar * K + ak);
                cp16(smem_u32(&Bs[buf ^ 1][bk][bc]), Bn + (size_t)bk * N + bc);
            }
            CP_COMMIT();
        }

#pragma unroll
        for (int kk = 0; kk < 2; kk++) {
            wmma::fragment<wmma::matrix_a, 16, 16, 8, wmma::precision::tf32, wmma::row_major> a[4];
            wmma::fragment<wmma::matrix_b, 16, 16, 8, wmma::precision::tf32, wmma::row_major> b[4];
#pragma unroll
            for (int mi = 0; mi < 4; mi++)
                wmma::load_matrix_sync(a[mi], &As[buf][wm * 64 + mi * 16][kk * 8], 20);
#pragma unroll
            for (int nj = 0; nj < 4; nj++)
                wmma::load_matrix_sync(b[nj], &Bs[buf][kk * 8][wn * 64 + nj * 16], 132);
#pragma unroll
            for (int mi = 0; mi < 4; mi++)
#pragma unroll
                for (int nj = 0; nj < 4; nj++)
                    wmma::mma_sync(c[mi][nj], a[mi], b[nj], c[mi][nj]);
        }

        CP_WAIT0();
        __syncthreads();
    }

    // ---- epilogue via per-warp staging ----
    const int r  = lane >> 1;
    const int cs = (lane & 1) * 8;
#pragma unroll
    for (int mi = 0; mi < 4; mi++) {
#pragma unroll
        for (int nj = 0; nj < 4; nj++) {
            wmma::store_matrix_sync(&stg[wid][0][0], c[mi][nj], 16, wmma::mem_row_major);
            __syncwarp();
            const int row = by * 128 + wm * 64 + mi * 16 + r;
            const int col = bx * 128 + wn * 64 + nj * 16 + cs;
            const size_t base = (size_t)row * N + col;
            float4 b0 = *(const float4*)(bias + col);
            float4 b1 = *(const float4*)(bias + col + 4);
            float v[8];
#pragma unroll
            for (int u = 0; u < 8; u++) v[u] = stg[wid][r][cs + u];
            v[0] += b0.x; v[1] += b0.y; v[2] += b0.z; v[3] += b0.w;
            v[4] += b1.x; v[5] += b1.y; v[6] += b1.z; v[7] += b1.w;
            if (EPI == 1) {
                float4 r0 = *(const float4*)(res + base);
                float4 r1 = *(const float4*)(res + base + 4);
                v[0] += r0.x; v[1] += r0.y; v[2] += r0.z; v[3] += r0.w;
                v[4] += r1.x; v[5] += r1.y; v[6] += r1.z; v[7] += r1.w;
            } else if (EPI == 2) {
#pragma unroll
                for (int u = 0; u < 8; u++) v[u] = gelu_f(v[u]);
            }
            *(float4*)(C + base)     = make_float4(v[0], v[1], v[2], v[3]);
            *(float4*)(C + base + 4) = make_float4(v[4], v[5], v[6], v[7]);
            __syncwarp();
        }
    }
}

// ---------------- flash attention (causal, fp32) ----------------
__global__ __launch_bounds__(64) void attn_kernel(
    const float* __restrict__ qkv, float* __restrict__ y)
{
    const int qt = blockIdx.x, h = blockIdx.y, b = blockIdx.z;
    const int tid = threadIdx.x;
    const int q0 = qt * 64;
    const int r = q0 + tid;

    __shared__ float q_s[64][100];
    __shared__ float k_s[16][96];
    __shared__ float v_s[16][96];

#pragma unroll
    for (int i = 0; i < 24; i++) {
        const int id = i * 64 + tid;
        const int row = id / 24, c = id % 24;
        float4 qv = *(const float4*)(qkv + (size_t)(b * TSEQ + q0 + row) * 2304 + h * 96 + c * 4);
        *(float4*)&q_s[row][c * 4] = qv;
    }

    float4 o4[24];
#pragma unroll
    for (int c = 0; c < 24; c++) o4[c] = make_float4(0.f, 0.f, 0.f, 0.f);
    float m = -1e30f, l = 0.f;
    const float scale = 0.10206207261596575f;

    const int nchunks = 4 * qt + 4;
    for (int jc = 0; jc < nchunks; ++jc) {
        __syncthreads();
        const int kb = jc * 16;
#pragma unroll
        for (int i = 0; i < 6; i++) {
            const int id = i * 64 + tid;
            const int row = id / 24, c = id % 24;
            const float* base = qkv + (size_t)(b * TSEQ + kb + row) * 2304 + h * 96 + c * 4;
            *(float4*)&k_s[row][c * 4] = *(const float4*)(base + 768);
            *(float4*)&v_s[row][c * 4] = *(const float4*)(base + 1536);
        }
        __syncthreads();

        float s[16];
#pragma unroll
        for (int j = 0; j < 16; j++) s[j] = 0.f;
#pragma unroll
        for (int c4 = 0; c4 < 24; c4++) {
            float4 q4 = *(const float4*)&q_s[tid][c4 * 4];
#pragma unroll
            for (int j = 0; j < 16; j++) {
                float4 k4 = *(const float4*)&k_s[j][c4 * 4];
                s[j] = fmaf(q4.x, k4.x, fmaf(q4.y, k4.y,
                       fmaf(q4.z, k4.z, fmaf(q4.w, k4.w, s[j]))));
            }
        }

        float mn = m;
#pragma unroll
        for (int j = 0; j < 16; j++) {
            const float sv = (kb + j <= r) ? s[j] * scale : -1e30f;
            s[j] = sv;
            mn = fmaxf(mn, sv);
        }
        const float f = __expf(m - mn);
        m = mn;
        float ls = 0.f;
#pragma unroll
        for (int j = 0; j < 16; j++) {
            const float p = __expf(s[j] - m);
            s[j] = p; ls += p;
        }
        l = l * f + ls;
#pragma unroll
        for (int c = 0; c < 24; c++) {
            o4[c].x *= f; o4[c].y *= f; o4[c].z *= f; o4[c].w *= f;
        }
#pragma unroll
        for (int j = 0; j < 16; j++) {
            const float p = s[j];
#pragma unroll
            for (int c = 0; c < 24; c++) {
                float4 v4 = *(const float4*)&v_s[j][c * 4];
                o4[c].x = fmaf(p, v4.x, o4[c].x);
                o4[c].y = fmaf(p, v4.y, o4[c].y);
                o4[c].z = fmaf(p, v4.z, o4[c].z);
                o4[c].w = fmaf(p, v4.w, o4[c].w);
            }
        }
    }

    const float inv = 1.0f / l;
    float* yr = y + (size_t)(b * TSEQ + r) * 768 + h * 96;
#pragma unroll
    for (int c = 0; c < 24; c++) {
        float4 v = o4[c];
        v.x *= inv; v.y *= inv; v.z *= inv; v.w *= inv;
        *(float4*)(yr + c * 4) = v;
    }
}

// ---------------- launch ----------------
extern "C" void kernel_launch(void* const* d_in, const int* in_sizes, int n_in,
                              void* d_out, int out_size)
{
    const float* x      = (const float*)d_in[0];
    const float* ln1_g  = (const float*)d_in[1];
    const float* ln1_b  = (const float*)d_in[2];
    const float* attn_w = (const float*)d_in[3];
    const float* attn_b = (const float*)d_in[4];
    const float* proj_w = (const float*)d_in[5];
    const float* proj_b = (const float*)d_in[6];
    const float* ln2_g  = (const float*)d_in[7];
    const float* ln2_b  = (const float*)d_in[8];
    const float* fc_w   = (const float*)d_in[9];
    const float* fc_b   = (const float*)d_in[10];
    const float* fc2_w  = (const float*)d_in[11];
    const float* fc2_b  = (const float*)d_in[12];
    float* out = (float*)d_out;

    float *h, *qkv, *y, *x1, *h2;
    cudaGetSymbolAddress((void**)&h,   g_h);
    cudaGetSymbolAddress((void**)&qkv, g_qkv);
    cudaGetSymbolAddress((void**)&y,   g_y);
    cudaGetSymbolAddress((void**)&x1,  g_x1);
    cudaGetSymbolAddress((void**)&h2,  g_h2);

    ln_kernel<<<MTOK, 256>>>(x, ln1_g, ln1_b, h);
    tgemm_kernel<0><<<dim3(2304 / 128, MTOK / 128), 128>>>(h, attn_w, attn_b, nullptr, qkv, 2304, 768);
    attn_kernel<<<dim3(TSEQ / 64, NHEAD, BATCH), 64>>>(qkv, y);
    tgemm_kernel<1><<<dim3(768 / 128, MTOK / 128), 128>>>(y, proj_w, proj_b, x, x1, 768, 768);
    ln_kernel<<<MTOK, 256>>>(x1, ln2_g, ln2_b, h);
    tgemm_kernel<2><<<dim3(3072 / 128, MTOK / 128), 128>>>(h, fc_w, fc_b, nullptr, h2, 3072, 768);
    tgemm_kernel<1><<<dim3(768 / 128, MTOK / 128), 128>>>(h2, fc2_w, fc2_b, x1, out, 768, 3072);
}

// round 4
// speedup vs baseline: 1.8296x; 1.1668x over previous
#include <cuda_runtime.h>
#include <math.h>
#include <mma.h>
#include <stdint.h>

using namespace nvcuda;

#define MTOK  16384
#define CDIM  768
#define TSEQ  1024
#define BATCH 16
#define NHEAD 8
#define HDIM  96

// ---------------- scratch (no allocation allowed) ----------------
__device__ float g_h  [(size_t)MTOK * CDIM];
__device__ float g_qkv[(size_t)MTOK * 3 * CDIM];
__device__ float g_y  [(size_t)MTOK * CDIM];
__device__ float g_x1 [(size_t)MTOK * CDIM];
__device__ float g_h2 [(size_t)MTOK * 4 * CDIM];
// RN-rounded tf32 weight copies
__device__ float g_wqkv[(size_t)CDIM * 3 * CDIM];
__device__ float g_wproj[(size_t)CDIM * CDIM];
__device__ float g_wfc [(size_t)CDIM * 4 * CDIM];
__device__ float g_wfc2[(size_t)4 * CDIM * CDIM];

__device__ __forceinline__ float t32(float x) { return wmma::__float_to_tf32(x); }

// ---------------- tf32 RN rounding (weights) ----------------
__global__ __launch_bounds__(256) void round_kernel(
    const float* __restrict__ src, float* __restrict__ dst, int n4)
{
    const int i = blockIdx.x * 256 + threadIdx.x;
    if (i < n4) {
        float4 v = ((const float4*)src)[i];
        v.x = t32(v.x); v.y = t32(v.y); v.z = t32(v.z); v.w = t32(v.w);
        ((float4*)dst)[i] = v;
    }
}

// ---------------- layernorm (tf32-rounded output) ----------------
__global__ __launch_bounds__(256) void ln_kernel(
    const float* __restrict__ x, const float* __restrict__ g,
    const float* __restrict__ b, float* __restrict__ out)
{
    const int row = blockIdx.x;
    const int tid = threadIdx.x;
    const float* xr = x + (size_t)row * CDIM;
    float vals[3];
    float s = 0.f, s2 = 0.f;
#pragma unroll
    for (int j = 0; j < 3; j++) {
        float t = xr[tid + 256 * j];
        vals[j] = t; s += t; s2 += t * t;
    }
#pragma unroll
    for (int o = 16; o > 0; o >>= 1) {
        s  += __shfl_xor_sync(0xffffffffu, s,  o);
        s2 += __shfl_xor_sync(0xffffffffu, s2, o);
    }
    __shared__ float rs[8], rs2[8];
    const int wid = tid >> 5, lane = tid & 31;
    if (lane == 0) { rs[wid] = s; rs2[wid] = s2; }
    __syncthreads();
    s = 0.f; s2 = 0.f;
#pragma unroll
    for (int w = 0; w < 8; w++) { s += rs[w]; s2 += rs2[w]; }
    const float mu  = s * (1.0f / CDIM);
    const float var = s2 * (1.0f / CDIM) - mu * mu;
    const float rstd = rsqrtf(var + 1e-5f);
    float* orow = out + (size_t)row * CDIM;
#pragma unroll
    for (int j = 0; j < 3; j++) {
        const int c = tid + 256 * j;
        orow[c] = t32((vals[j] - mu) * rstd * g[c] + b[c]);
    }
}

// ---------------- TF32 tensor-core GEMM (unchanged mainloop) ----------------
__device__ __forceinline__ float gelu_f(float x) {
    const float x3 = x * x * x;
    return 0.5f * x * (1.0f + tanhf(0.7978845608028654f * (x + 0.044715f * x3)));
}

__device__ __forceinline__ uint32_t smem_u32(const void* p) {
    return (uint32_t)__cvta_generic_to_shared(p);
}
__device__ __forceinline__ void cp16(uint32_t dst, const void* src) {
    asm volatile("cp.async.cg.shared.global [%0], [%1], 16;\n" :: "r"(dst), "l"(src));
}
#define CP_COMMIT() asm volatile("cp.async.commit_group;\n" ::: "memory")
#define CP_WAIT0()  asm volatile("cp.async.wait_group 0;\n" ::: "memory")

// EPI: 0 = bias, 1 = bias+residual, 2 = bias+gelu(rounded)
template <int EPI>
__global__ __launch_bounds__(128) void tgemm_kernel(
    const float* __restrict__ A, const float* __restrict__ B,
    const float* __restrict__ bias, const float* __restrict__ res,
    float* __restrict__ C, int N, int K)
{
    __shared__ float As[2][128][20];
    __shared__ float Bs[2][16][132];
    __shared__ float stg[4][16][16];

    const int tid  = threadIdx.x;
    const int wid  = tid >> 5, lane = tid & 31;
    const int wm   = wid >> 1;
    const int wn   = wid & 1;
    const int bx   = blockIdx.x, by = blockIdx.y;

    wmma::fragment<wmma::accumulator, 16, 16, 8, float> c[4][4];
#pragma unroll
    for (int i = 0; i < 4; i++)
#pragma unroll
        for (int j = 0; j < 4; j++) wmma::fill_fragment(c[i][j], 0.0f);

    const float* Agm = A + (size_t)(by * 128) * K;
    const float* Bgm = B + bx * 128;

    const int nk = K >> 4;

#pragma unroll
    for (int it = 0; it < 4; it++) {
        const int idx = it * 128 + tid;
        const int ar = idx >> 2, ak = (idx & 3) * 4;
        const int bk = idx >> 5, bc = (idx & 31) * 4;
        cp16(smem_u32(&As[0][ar][ak]), Agm + (size_t)ar * K + ak);
        cp16(smem_u32(&Bs[0][bk][bc]), Bgm + (size_t)bk * N + bc);
    }
    CP_COMMIT();
    CP_WAIT0();
    __syncthreads();

    for (int kt = 0; kt < nk; ++kt) {
        const int buf = kt & 1;
        if (kt + 1 < nk) {
            const float* An = Agm + (kt + 1) * 16;
            const float* Bn = Bgm + (size_t)((kt + 1) * 16) * N;
#pragma unroll
            for (int it = 0; it < 4; it++) {
                const int idx = it * 128 + tid;
                const int ar = idx >> 2, ak = (idx & 3) * 4;
                const int bk = idx >> 5, bc = (idx & 31) * 4;
                cp16(smem_u32(&As[buf ^ 1][ar][ak]), An + (size_t)ar * K + ak);
                cp16(smem_u32(&Bs[buf ^ 1][bk][bc]), Bn + (size_t)bk * N + bc);
            }
            CP_COMMIT();
        }

#pragma unroll
        for (int kk = 0; kk < 2; kk++) {
            wmma::fragment<wmma::matrix_a, 16, 16, 8, wmma::precision::tf32, wmma::row_major> a[4];
            wmma::fragment<wmma::matrix_b, 16, 16, 8, wmma::precision::tf32, wmma::row_major> b[4];
#pragma unroll
            for (int mi = 0; mi < 4; mi++)
                wmma::load_matrix_sync(a[mi], &As[buf][wm * 64 + mi * 16][kk * 8], 20);
#pragma unroll
            for (int nj = 0; nj < 4; nj++)
                wmma::load_matrix_sync(b[nj], &Bs[buf][kk * 8][wn * 64 + nj * 16], 132);
#pragma unroll
            for (int mi = 0; mi < 4; mi++)
#pragma unroll
                for (int nj = 0; nj < 4; nj++)
                    wmma::mma_sync(c[mi][nj], a[mi], b[nj], c[mi][nj]);
        }

        CP_WAIT0();
        __syncthreads();
    }

    const int r  = lane >> 1;
    const int cs = (lane & 1) * 8;
#pragma unroll
    for (int mi = 0; mi < 4; mi++) {
#pragma unroll
        for (int nj = 0; nj < 4; nj++) {
            wmma::store_matrix_sync(&stg[wid][0][0], c[mi][nj], 16, wmma::mem_row_major);
            __syncwarp();
            const int row = by * 128 + wm * 64 + mi * 16 + r;
            const int col = bx * 128 + wn * 64 + nj * 16 + cs;
            const size_t base = (size_t)row * N + col;
            float4 b0 = *(const float4*)(bias + col);
            float4 b1 = *(const float4*)(bias + col + 4);
            float v[8];
#pragma unroll
            for (int u = 0; u < 8; u++) v[u] = stg[wid][r][cs + u];
            v[0] += b0.x; v[1] += b0.y; v[2] += b0.z; v[3] += b0.w;
            v[4] += b1.x; v[5] += b1.y; v[6] += b1.z; v[7] += b1.w;
            if (EPI == 1) {
                float4 r0 = *(const float4*)(res + base);
                float4 r1 = *(const float4*)(res + base + 4);
                v[0] += r0.x; v[1] += r0.y; v[2] += r0.z; v[3] += r0.w;
                v[4] += r1.x; v[5] += r1.y; v[6] += r1.z; v[7] += r1.w;
            } else if (EPI == 2) {
#pragma unroll
                for (int u = 0; u < 8; u++) v[u] = t32(gelu_f(v[u]));
            }
            *(float4*)(C + base)     = make_float4(v[0], v[1], v[2], v[3]);
            *(float4*)(C + base + 4) = make_float4(v[4], v[5], v[6], v[7]);
            __syncwarp();
        }
    }
}

// ---------------- tensor-core flash attention (causal, tf32) ----------------
// 64-query tile, 256 threads (8 warps: 4 m-groups x 2 n-groups), 64-key chunks.
struct AttnSmem {
    float Qs[64][100];
    float Ks[64][100];
    float Vs[64][100];
    float Os[64][100];
    float Ss[64][68];
    float m_s[64], l_s[64], f_s[64];
};

__global__ __launch_bounds__(256) void attn_kernel(
    const float* __restrict__ qkv, float* __restrict__ y)
{
    extern __shared__ char smem_raw[];
    AttnSmem& sm = *reinterpret_cast<AttnSmem*>(smem_raw);

    const int qt = blockIdx.x, h = blockIdx.y, b = blockIdx.z;
    const int tid = threadIdx.x;
    const int wid = tid >> 5;
    const int wm = wid >> 1;      // 0..3  (16-row group)
    const int wn = wid & 1;       // 0..1
    const int q0 = qt * 64;
    const float scale = 0.10206207261596575f;  // 1/sqrt(96)

    // ---- load Q tile (rounded), zero O, init stats ----
#pragma unroll
    for (int i = 0; i < 6; i++) {
        const int idx = i * 256 + tid;          // 0..1535
        const int row = idx / 24, c = idx % 24;
        float4 v = *(const float4*)(qkv + (size_t)(b * TSEQ + q0 + row) * 2304 + h * 96 + c * 4);
        v.x = t32(v.x); v.y = t32(v.y); v.z = t32(v.z); v.w = t32(v.w);
        *(float4*)&sm.Qs[row][c * 4] = v;
    }
#pragma unroll
    for (int i = 0; i < 25; i++) {
        const int idx = i * 256 + tid;          // 0..6399
        ((float*)sm.Os)[idx] = 0.f;
    }
    if (tid < 64) { sm.m_s[tid] = -3e38f; sm.l_s[tid] = 0.f; }

    for (int jc = 0; jc <= qt; ++jc) {
        const int kb = jc * 64;
        __syncthreads();   // prev PV done with Ks/Vs; stats/Q visible on first iter

        // ---- load K/V chunk (rounded) ----
#pragma unroll
        for (int i = 0; i < 6; i++) {
            const int idx = i * 256 + tid;
            const int row = idx / 24, c = idx % 24;
            const float* base = qkv + (size_t)(b * TSEQ + kb + row) * 2304 + h * 96 + c * 4;
            float4 kv = *(const float4*)(base + 768);
            float4 vv = *(const float4*)(base + 1536);
            kv.x = t32(kv.x); kv.y = t32(kv.y); kv.z = t32(kv.z); kv.w = t32(kv.w);
            vv.x = t32(vv.x); vv.y = t32(vv.y); vv.z = t32(vv.z); vv.w = t32(vv.w);
            *(float4*)&sm.Ks[row][c * 4] = kv;
            *(float4*)&sm.Vs[row][c * 4] = vv;
        }
        __syncthreads();

        // ---- S = Q K^T  (warp: 16 rows x 32 cols) ----
        {
            wmma::fragment<wmma::accumulator, 16, 16, 8, float> sc[2];
            wmma::fill_fragment(sc[0], 0.f);
            wmma::fill_fragment(sc[1], 0.f);
#pragma unroll
            for (int ks = 0; ks < 12; ks++) {
                wmma::fragment<wmma::matrix_a, 16, 16, 8, wmma::precision::tf32, wmma::row_major> af;
                wmma::load_matrix_sync(af, &sm.Qs[wm * 16][ks * 8], 100);
#pragma unroll
                for (int j = 0; j < 2; j++) {
                    wmma::fragment<wmma::matrix_b, 16, 16, 8, wmma::precision::tf32, wmma::col_major> bf;
                    wmma::load_matrix_sync(bf, &sm.Ks[wn * 32 + j * 16][ks * 8], 100);
                    wmma::mma_sync(sc[j], af, bf, sc[j]);
                }
            }
#pragma unroll
            for (int j = 0; j < 2; j++)
                wmma::store_matrix_sync(&sm.Ss[wm * 16][wn * 32 + j * 16], sc[j], 68, wmma::mem_row_major);
        }
        __syncthreads();

        // ---- online softmax (4 threads per row, 16 cols each) ----
        {
            const int row = tid >> 2;
            const int q4  = tid & 3;
            const int gq  = q0 + row;
            const bool diag = (jc == qt);
            const float m_old = sm.m_s[row];
            float sv[16];
            float mloc = -3e38f;
#pragma unroll
            for (int j = 0; j < 16; j++) {
                const int cc = q4 * 16 + j;
                float s = sm.Ss[row][cc] * scale;
                if (diag && (kb + cc > gq)) s = -3e38f;
                sv[j] = s;
                mloc = fmaxf(mloc, s);
            }
            mloc = fmaxf(mloc, __shfl_xor_sync(0xffffffffu, mloc, 1));
            mloc = fmaxf(mloc, __shfl_xor_sync(0xffffffffu, mloc, 2));
            const float m_new = fmaxf(m_old, mloc);
            float ls = 0.f;
#pragma unroll
            for (int j = 0; j < 16; j++) {
                const float p = __expf(sv[j] - m_new);
                ls += p;
                sm.Ss[row][q4 * 16 + j] = t32(p);
            }
            ls += __shfl_xor_sync(0xffffffffu, ls, 1);
            ls += __shfl_xor_sync(0xffffffffu, ls, 2);
            if (q4 == 0) {
                const float f = __expf(m_old - m_new);
                sm.f_s[row] = f;
                sm.m_s[row] = m_new;
                sm.l_s[row] = sm.l_s[row] * f + ls;
            }
        }
        __syncthreads();

        // ---- rescale O by f ----
#pragma unroll
        for (int i = 0; i < 25; i++) {
            const int idx = i * 256 + tid;
            const int row = idx / 100;
            ((float*)sm.Os)[idx] *= sm.f_s[row];
        }
        __syncthreads();

        // ---- O += P V  (warp: 16 rows x 48 cols) ----
        {
            wmma::fragment<wmma::accumulator, 16, 16, 8, float> oc[3];
#pragma unroll
            for (int j = 0; j < 3; j++)
                wmma::load_matrix_sync(oc[j], &sm.Os[wm * 16][wn * 48 + j * 16], 100, wmma::mem_row_major);
#pragma unroll
            for (int ks = 0; ks < 8; ks++) {
                wmma::fragment<wmma::matrix_a, 16, 16, 8, wmma::precision::tf32, wmma::row_major> pf;
                wmma::load_matrix_sync(pf, &sm.Ss[wm * 16][ks * 8], 68);
#pragma unroll
                for (int j = 0; j < 3; j++) {
                    wmma::fragment<wmma::matrix_b, 16, 16, 8, wmma::precision::tf32, wmma::row_major> vf;
                    wmma::load_matrix_sync(vf, &sm.Vs[ks * 8][wn * 48 + j * 16], 100);
                    wmma::mma_sync(oc[j], pf, vf, oc[j]);
                }
            }
#pragma unroll
            for (int j = 0; j < 3; j++)
                wmma::store_matrix_sync(&sm.Os[wm * 16][wn * 48 + j * 16], oc[j], 100, wmma::mem_row_major);
        }
    }
    __syncthreads();

    // ---- write y = O / l (rounded for proj GEMM) ----
#pragma unroll
    for (int i = 0; i < 6; i++) {
        const int idx = i * 256 + tid;
        const int row = idx / 24, c = idx % 24;
        const float inv = 1.0f / sm.l_s[row];
        float4 v = *(const float4*)&sm.Os[row][c * 4];
        v.x = t32(v.x * inv); v.y = t32(v.y * inv);
        v.z = t32(v.z * inv); v.w = t32(v.w * inv);
        *(float4*)(y + (size_t)(b * TSEQ + q0 + row) * 768 + h * 96 + c * 4) = v;
    }
}

// ---------------- launch ----------------
extern "C" void kernel_launch(void* const* d_in, const int* in_sizes, int n_in,
                              void* d_out, int out_size)
{
    const float* x      = (const float*)d_in[0];
    const float* ln1_g  = (const float*)d_in[1];
    const float* ln1_b  = (const float*)d_in[2];
    const float* attn_w = (const float*)d_in[3];
    const float* attn_b = (const float*)d_in[4];
    const float* proj_w = (const float*)d_in[5];
    const float* proj_b = (const float*)d_in[6];
    const float* ln2_g  = (const float*)d_in[7];
    const float* ln2_b  = (const float*)d_in[8];
    const float* fc_w   = (const float*)d_in[9];
    const float* fc_b   = (const float*)d_in[10];
    const float* fc2_w  = (const float*)d_in[11];
    const float* fc2_b  = (const float*)d_in[12];
    float* out = (float*)d_out;

    float *h, *qkv, *y, *x1, *h2, *wqkv, *wproj, *wfc, *wfc2;
    cudaGetSymbolAddress((void**)&h,    g_h);
    cudaGetSymbolAddress((void**)&qkv,  g_qkv);
    cudaGetSymbolAddress((void**)&y,    g_y);
    cudaGetSymbolAddress((void**)&x1,   g_x1);
    cudaGetSymbolAddress((void**)&h2,   g_h2);
    cudaGetSymbolAddress((void**)&wqkv, g_wqkv);
    cudaGetSymbolAddress((void**)&wproj,g_wproj);
    cudaGetSymbolAddress((void**)&wfc,  g_wfc);
    cudaGetSymbolAddress((void**)&wfc2, g_wfc2);

    static bool attr_set = false;
    if (!attr_set) {
        cudaFuncSetAttribute(attn_kernel, cudaFuncAttributeMaxDynamicSharedMemorySize,
                             (int)sizeof(AttnSmem));
        attr_set = true;
    }

    // RN-round weights to tf32 (removes HW-truncation error)
    round_kernel<<<(CDIM * 3 * CDIM / 4 + 255) / 256, 256>>>(attn_w, wqkv, CDIM * 3 * CDIM / 4);
    round_kernel<<<(CDIM * CDIM / 4 + 255) / 256, 256>>>(proj_w, wproj, CDIM * CDIM / 4);
    round_kernel<<<(CDIM * 4 * CDIM / 4 + 255) / 256, 256>>>(fc_w, wfc, CDIM * 4 * CDIM / 4);
    round_kernel<<<(4 * CDIM * CDIM / 4 + 255) / 256, 256>>>(fc2_w, wfc2, 4 * CDIM * CDIM / 4);

    ln_kernel<<<MTOK, 256>>>(x, ln1_g, ln1_b, h);
    tgemm_kernel<0><<<dim3(2304 / 128, MTOK / 128), 128>>>(h, wqkv, attn_b, nullptr, qkv, 2304, 768);
    attn_kernel<<<dim3(TSEQ / 64, NHEAD, BATCH), 256, sizeof(AttnSmem)>>>(qkv, y);
    tgemm_kernel<1><<<dim3(768 / 128, MTOK / 128), 128>>>(y, wproj, proj_b, x, x1, 768, 768);
    ln_kernel<<<MTOK, 256>>>(x1, ln2_g, ln2_b, h);
    tgemm_kernel<2><<<dim3(3072 / 128, MTOK / 128), 128>>>(h, wfc, fc_b, nullptr, h2, 3072, 768);
    tgemm_kernel<1><<<dim3(768 / 128, MTOK / 128), 128>>>(h2, wfc2, fc2_b, x1, out, 768, 3072);
}

// round 6
// speedup vs baseline: 5.7766x; 3.1572x over previous
#include <cuda_runtime.h>
#include <cuda_fp16.h>
#include <math.h>
#include <mma.h>
#include <stdint.h>

using namespace nvcuda;

#define MTOK  16384
#define CDIM  768
#define TSEQ  1024
#define BATCH 16
#define NHEAD 8
#define HDIM  96

// ================= scratch (no allocation allowed) =================
__device__ __half g_h  [(size_t)MTOK * CDIM];        // ln output (fp16)
__device__ __half g_qkv[(size_t)MTOK * 3 * CDIM];    // qkv (fp16)
__device__ __half g_y  [(size_t)MTOK * CDIM];        // attn output (fp16)
__device__ float  g_x1 [(size_t)MTOK * CDIM];        // post-attn residual (f32)
__device__ __half g_h2 [(size_t)MTOK * 4 * CDIM];    // gelu(fc) (fp16)
// fp16 weights (same [K,N] layout as input)
__device__ __half g_wqkv[(size_t)CDIM * 3 * CDIM];
__device__ __half g_wproj[(size_t)CDIM * CDIM];
__device__ __half g_wfc [(size_t)CDIM * 4 * CDIM];
__device__ __half g_wfc2[(size_t)4 * CDIM * CDIM];

__device__ __forceinline__ float gelu_f(float x) {
    const float x3 = x * x * x;
    return 0.5f * x * (1.0f + tanhf(0.7978845608028654f * (x + 0.044715f * x3)));
}
__device__ __forceinline__ uint32_t smem_u32(const void* p) {
    return (uint32_t)__cvta_generic_to_shared(p);
}
__device__ __forceinline__ void cp16(uint32_t dst, const void* src) {
    asm volatile("cp.async.cg.shared.global [%0], [%1], 16;\n" :: "r"(dst), "l"(src));
}
#define CP_COMMIT() asm volatile("cp.async.commit_group;\n" ::: "memory")
#define CP_WAIT0()  asm volatile("cp.async.wait_group 0;\n" ::: "memory")

// ================= weight f32 -> fp16 =================
__global__ __launch_bounds__(256) void wconv_kernel(
    const float* __restrict__ src, __half* __restrict__ dst, int n4)
{
    const int i = blockIdx.x * 256 + threadIdx.x;
    if (i < n4) {
        float4 v = ((const float4*)src)[i];
        __half2 a = __floats2half2_rn(v.x, v.y);
        __half2 b = __floats2half2_rn(v.z, v.w);
        *(uint2*)(dst + (size_t)i * 4) = make_uint2(
            *(uint32_t*)&a, *(uint32_t*)&b);
    }
}

// ================= layernorm (f32 in -> fp16 out) =================
__global__ __launch_bounds__(256) void ln_kernel(
    const float* __restrict__ x, const float* __restrict__ g,
    const float* __restrict__ b, __half* __restrict__ out)
{
    const int row = blockIdx.x;
    const int tid = threadIdx.x;
    const float* xr = x + (size_t)row * CDIM;
    float vals[3];
    float s = 0.f, s2 = 0.f;
#pragma unroll
    for (int j = 0; j < 3; j++) {
        float t = xr[tid + 256 * j];
        vals[j] = t; s += t; s2 += t * t;
    }
#pragma unroll
    for (int o = 16; o > 0; o >>= 1) {
        s  += __shfl_xor_sync(0xffffffffu, s,  o);
        s2 += __shfl_xor_sync(0xffffffffu, s2, o);
    }
    __shared__ float rs[8], rs2[8];
    const int wid = tid >> 5, lane = tid & 31;
    if (lane == 0) { rs[wid] = s; rs2[wid] = s2; }
    __syncthreads();
    s = 0.f; s2 = 0.f;
#pragma unroll
    for (int w = 0; w < 8; w++) { s += rs[w]; s2 += rs2[w]; }
    const float mu  = s * (1.0f / CDIM);
    const float var = s2 * (1.0f / CDIM) - mu * mu;
    const float rstd = rsqrtf(var + 1e-5f);
#pragma unroll
    for (int j = 0; j < 3; j++) {
        const int c = tid + 256 * j;
        out[(size_t)row * CDIM + c] = __float2half_rn((vals[j] - mu) * rstd * g[c] + b[c]);
    }
}

// ================= fp16 tensor-core GEMM =================
// block 128x128, BK=32, 128 threads (4 warps 2x2), warp tile 64x64,
// cp.async double-buffered fp16 smem.
// EPI: 0 = bias -> half ; 1 = bias+res(f32) -> f32 ; 2 = bias+gelu -> half
template <int EPI>
__global__ __launch_bounds__(128) void hgemm_kernel(
    const __half* __restrict__ A, const __half* __restrict__ B,
    const float* __restrict__ bias, const float* __restrict__ res,
    float* __restrict__ Cf, __half* __restrict__ Ch, int N, int K)
{
    __shared__ __half As[2][128][40];   // [m][k], pad 8 (80B rows)
    __shared__ __half Bs[2][32][136];   // [k][n], pad 8 (272B rows)
    __shared__ float  stg[4][16][16];

    const int tid  = threadIdx.x;
    const int wid  = tid >> 5, lane = tid & 31;
    const int wm   = wid >> 1;
    const int wn   = wid & 1;
    const int bx   = blockIdx.x, by = blockIdx.y;

    wmma::fragment<wmma::accumulator, 16, 16, 16, float> c[4][4];
#pragma unroll
    for (int i = 0; i < 4; i++)
#pragma unroll
        for (int j = 0; j < 4; j++) wmma::fill_fragment(c[i][j], 0.0f);

    const __half* Agm = A + (size_t)(by * 128) * K;
    const __half* Bgm = B + bx * 128;

    const int nk = K >> 5;

    // tile copy: A = 512 chunks of 16B (128r x 4), B = 512 chunks (32r x 16)
#pragma unroll
    for (int it = 0; it < 4; it++) {
        const int idx = it * 128 + tid;
        const int ar = idx >> 2, ak = (idx & 3) * 8;
        const int bk = idx >> 4, bc = (idx & 15) * 8;
        cp16(smem_u32(&As[0][ar][ak]), Agm + (size_t)ar * K + ak);
        cp16(smem_u32(&Bs[0][bk][bc]), Bgm + (size_t)bk * N + bc);
    }
    CP_COMMIT();
    CP_WAIT0();
    __syncthreads();

    for (int kt = 0; kt < nk; ++kt) {
        const int buf = kt & 1;
        if (kt + 1 < nk) {
            const __half* An = Agm + (kt + 1) * 32;
            const __half* Bn = Bgm + (size_t)((kt + 1) * 32) * N;
#pragma unroll
            for (int it = 0; it < 4; it++) {
                const int idx = it * 128 + tid;
                const int ar = idx >> 2, ak = (idx & 3) * 8;
                const int bk = idx >> 4, bc = (idx & 15) * 8;
                cp16(smem_u32(&As[buf ^ 1][ar][ak]), An + (size_t)ar * K + ak);
                cp16(smem_u32(&Bs[buf ^ 1][bk][bc]), Bn + (size_t)bk * N + bc);
            }
            CP_COMMIT();
        }

#pragma unroll
        for (int ks = 0; ks < 2; ks++) {
            wmma::fragment<wmma::matrix_a, 16, 16, 16, __half, wmma::row_major> a[4];
            wmma::fragment<wmma::matrix_b, 16, 16, 16, __half, wmma::row_major> b[4];
#pragma unroll
            for (int mi = 0; mi < 4; mi++)
                wmma::load_matrix_sync(a[mi], &As[buf][wm * 64 + mi * 16][ks * 16], 40);
#pragma unroll
            for (int nj = 0; nj < 4; nj++)
                wmma::load_matrix_sync(b[nj], &Bs[buf][ks * 16][wn * 64 + nj * 16], 136);
#pragma unroll
            for (int mi = 0; mi < 4; mi++)
#pragma unroll
                for (int nj = 0; nj < 4; nj++)
                    wmma::mma_sync(c[mi][nj], a[mi], b[nj], c[mi][nj]);
        }

        CP_WAIT0();
        __syncthreads();
    }

    // ---- epilogue via per-warp staging ----
    const int r  = lane >> 1;
    const int cs = (lane & 1) * 8;
#pragma unroll
    for (int mi = 0; mi < 4; mi++) {
#pragma unroll
        for (int nj = 0; nj < 4; nj++) {
            wmma::store_matrix_sync(&stg[wid][0][0], c[mi][nj], 16, wmma::mem_row_major);
            __syncwarp();
            const int row = by * 128 + wm * 64 + mi * 16 + r;
            const int col = bx * 128 + wn * 64 + nj * 16 + cs;
            const size_t base = (size_t)row * N + col;
            float4 b0 = *(const float4*)(bias + col);
            float4 b1 = *(const float4*)(bias + col + 4);
            float v[8];
#pragma unroll
            for (int u = 0; u < 8; u++) v[u] = stg[wid][r][cs + u];
            v[0] += b0.x; v[1] += b0.y; v[2] += b0.z; v[3] += b0.w;
            v[4] += b1.x; v[5] += b1.y; v[6] += b1.z; v[7] += b1.w;
            if (EPI == 1) {
                float4 r0 = *(const float4*)(res + base);
                float4 r1 = *(const float4*)(res + base + 4);
                v[0] += r0.x; v[1] += r0.y; v[2] += r0.z; v[3] += r0.w;
                v[4] += r1.x; v[5] += r1.y; v[6] += r1.z; v[7] += r1.w;
                *(float4*)(Cf + base)     = make_float4(v[0], v[1], v[2], v[3]);
                *(float4*)(Cf + base + 4) = make_float4(v[4], v[5], v[6], v[7]);
            } else {
                if (EPI == 2) {
#pragma unroll
                    for (int u = 0; u < 8; u++) v[u] = gelu_f(v[u]);
                }
                __half2 h0 = __floats2half2_rn(v[0], v[1]);
                __half2 h1 = __floats2half2_rn(v[2], v[3]);
                __half2 h2 = __floats2half2_rn(v[4], v[5]);
                __half2 h3 = __floats2half2_rn(v[6], v[7]);
                *(uint4*)(Ch + base) = make_uint4(
                    *(uint32_t*)&h0, *(uint32_t*)&h1, *(uint32_t*)&h2, *(uint32_t*)&h3);
            }
            __syncwarp();
        }
    }
}

// ================= fp16 tensor-core flash attention (causal) =================
// 64-query tile, 256 threads (8 warps: 4 m x 2 n), 64-key chunks.
struct AttnSmem {
    __half Qs[64][104];
    __half Ks[64][104];
    __half Vs[64][104];
    __half Ps[64][72];
    float  Ss[64][68];
    float  Os[64][100];
    float  m_s[64], l_s[64], f_s[64];
};

__global__ __launch_bounds__(256) void attn_kernel(
    const __half* __restrict__ qkv, __half* __restrict__ y)
{
    extern __shared__ char smem_raw[];
    AttnSmem& sm = *reinterpret_cast<AttnSmem*>(smem_raw);

    const int qt = blockIdx.x, h = blockIdx.y, b = blockIdx.z;
    const int tid = threadIdx.x;
    const int wid = tid >> 5;
    const int wm = wid >> 1;
    const int wn = wid & 1;
    const int q0 = qt * 64;
    const float scale = 0.10206207261596575f;  // 1/sqrt(96)

    // ---- load Q tile (64 rows x 96 halfs = 768 x 16B chunks) ----
#pragma unroll
    for (int i = 0; i < 3; i++) {
        const int idx = i * 256 + tid;
        const int row = idx / 12, c = (idx % 12) * 8;
        *(uint4*)&sm.Qs[row][c] =
            *(const uint4*)(qkv + (size_t)(b * TSEQ + q0 + row) * 2304 + h * 96 + c);
    }
#pragma unroll
    for (int i = 0; i < 25; i++)
        ((float*)sm.Os)[i * 256 + tid] = 0.f;
    if (tid < 64) { sm.m_s[tid] = -3e38f; sm.l_s[tid] = 0.f; }

    for (int jc = 0; jc <= qt; ++jc) {
        const int kb = jc * 64;
        __syncthreads();

#pragma unroll
        for (int i = 0; i < 3; i++) {
            const int idx = i * 256 + tid;
            const int row = idx / 12, c = (idx % 12) * 8;
            const __half* base = qkv + (size_t)(b * TSEQ + kb + row) * 2304 + h * 96 + c;
            *(uint4*)&sm.Ks[row][c] = *(const uint4*)(base + 768);
            *(uint4*)&sm.Vs[row][c] = *(const uint4*)(base + 1536);
        }
        __syncthreads();

        // ---- S = Q K^T ----
        {
            wmma::fragment<wmma::accumulator, 16, 16, 16, float> sc[2];
            wmma::fill_fragment(sc[0], 0.f);
            wmma::fill_fragment(sc[1], 0.f);
#pragma unroll
            for (int ks = 0; ks < 6; ks++) {
                wmma::fragment<wmma::matrix_a, 16, 16, 16, __half, wmma::row_major> af;
                wmma::load_matrix_sync(af, &sm.Qs[wm * 16][ks * 16], 104);
#pragma unroll
                for (int j = 0; j < 2; j++) {
                    wmma::fragment<wmma::matrix_b, 16, 16, 16, __half, wmma::col_major> bf;
                    wmma::load_matrix_sync(bf, &sm.Ks[wn * 32 + j * 16][ks * 16], 104);
                    wmma::mma_sync(sc[j], af, bf, sc[j]);
                }
            }
#pragma unroll
            for (int j = 0; j < 2; j++)
                wmma::store_matrix_sync(&sm.Ss[wm * 16][wn * 32 + j * 16], sc[j], 68, wmma::mem_row_major);
        }
        __syncthreads();

        // ---- online softmax (4 threads/row) ----
        {
            const int row = tid >> 2;
            const int q4  = tid & 3;
            const int gq  = q0 + row;
            const bool diag = (jc == qt);
            const float m_old = sm.m_s[row];
            float sv[16];
            float mloc = -3e38f;
#pragma unroll
            for (int j = 0; j < 16; j++) {
                const int cc = q4 * 16 + j;
                float s = sm.Ss[row][cc] * scale;
                if (diag && (kb + cc > gq)) s = -3e38f;
                sv[j] = s;
                mloc = fmaxf(mloc, s);
            }
            mloc = fmaxf(mloc, __shfl_xor_sync(0xffffffffu, mloc, 1));
            mloc = fmaxf(mloc, __shfl_xor_sync(0xffffffffu, mloc, 2));
            const float m_new = fmaxf(m_old, mloc);
            float ls = 0.f;
#pragma unroll
            for (int j = 0; j < 16; j += 2) {
                const float p0 = __expf(sv[j]     - m_new);
                const float p1 = __expf(sv[j + 1] - m_new);
                ls += p0 + p1;
                *(__half2*)&sm.Ps[row][q4 * 16 + j] = __floats2half2_rn(p0, p1);
            }
            ls += __shfl_xor_sync(0xffffffffu, ls, 1);
            ls += __shfl_xor_sync(0xffffffffu, ls, 2);
            if (q4 == 0) {
                const float f = __expf(m_old - m_new);
                sm.f_s[row] = f;
                sm.m_s[row] = m_new;
                sm.l_s[row] = sm.l_s[row] * f + ls;
            }
        }
        __syncthreads();

        // ---- rescale O ----
#pragma unroll
        for (int i = 0; i < 25; i++) {
            const int idx = i * 256 + tid;
            ((float*)sm.Os)[idx] *= sm.f_s[idx / 100];
        }
        __syncthreads();

        // ---- O += P V ----
        {
            wmma::fragment<wmma::accumulator, 16, 16, 16, float> oc[3];
#pragma unroll
            for (int j = 0; j < 3; j++)
                wmma::load_matrix_sync(oc[j], &sm.Os[wm * 16][wn * 48 + j * 16], 100, wmma::mem_row_major);
#pragma unroll
            for (int ks = 0; ks < 4; ks++) {
                wmma::fragment<wmma::matrix_a, 16, 16, 16, __half, wmma::row_major> pf;
                wmma::load_matrix_sync(pf, &sm.Ps[wm * 16][ks * 16], 72);
#pragma unroll
                for (int j = 0; j < 3; j++) {
                    wmma::fragment<wmma::matrix_b, 16, 16, 16, __half, wmma::row_major> vf;
                    wmma::load_matrix_sync(vf, &sm.Vs[ks * 16][wn * 48 + j * 16], 104);
                    wmma::mma_sync(oc[j], pf, vf, oc[j]);
                }
            }
#pragma unroll
            for (int j = 0; j < 3; j++)
                wmma::store_matrix_sync(&sm.Os[wm * 16][wn * 48 + j * 16], oc[j], 100, wmma::mem_row_major);
        }
    }
    __syncthreads();

    // ---- write y = O / l (fp16) ----
#pragma unroll
    for (int i = 0; i < 3; i++) {
        const int idx = i * 256 + tid;
        const int row = idx / 12, c = (idx % 12) * 8;
        const float inv = 1.0f / sm.l_s[row];
        const float* o = &sm.Os[row][c];
        __half2 h0 = __floats2half2_rn(o[0] * inv, o[1] * inv);
        __half2 h1 = __floats2half2_rn(o[2] * inv, o[3] * inv);
        __half2 h2 = __floats2half2_rn(o[4] * inv, o[5] * inv);
        __half2 h3 = __floats2half2_rn(o[6] * inv, o[7] * inv);
        *(uint4*)(y + (size_t)(b * TSEQ + q0 + row) * 768 + h * 96 + c) = make_uint4(
            *(uint32_t*)&h0, *(uint32_t*)&h1, *(uint32_t*)&h2, *(uint32_t*)&h3);
    }
}

// ================= launch =================
extern "C" void kernel_launch(void* const* d_in, const int* in_sizes, int n_in,
                              void* d_out, int out_size)
{
    const float* x      = (const float*)d_in[0];
    const float* ln1_g  = (const float*)d_in[1];
    const float* ln1_b  = (const float*)d_in[2];
    const float* attn_w = (const float*)d_in[3];
    const float* attn_b = (const float*)d_in[4];
    const float* proj_w = (const float*)d_in[5];
    const float* proj_b = (const float*)d_in[6];
    const float* ln2_g  = (const float*)d_in[7];
    const float* ln2_b  = (const float*)d_in[8];
    const float* fc_w   = (const float*)d_in[9];
    const float* fc_b   = (const float*)d_in[10];
    const float* fc2_w  = (const float*)d_in[11];
    const float* fc2_b  = (const float*)d_in[12];
    float* out = (float*)d_out;

    __half *h, *qkv, *y, *h2, *wqkv, *wproj, *wfc, *wfc2;
    float *x1;
    cudaGetSymbolAddress((void**)&h,    g_h);
    cudaGetSymbolAddress((void**)&qkv,  g_qkv);
    cudaGetSymbolAddress((void**)&y,    g_y);
    cudaGetSymbolAddress((void**)&x1,   g_x1);
    cudaGetSymbolAddress((void**)&h2,   g_h2);
    cudaGetSymbolAddress((void**)&wqkv, g_wqkv);
    cudaGetSymbolAddress((void**)&wproj,g_wproj);
    cudaGetSymbolAddress((void**)&wfc,  g_wfc);
    cudaGetSymbolAddress((void**)&wfc2, g_wfc2);

    static bool attr_set = false;
    if (!attr_set) {
        cudaFuncSetAttribute(attn_kernel, cudaFuncAttributeMaxDynamicSharedMemorySize,
                             (int)sizeof(AttnSmem));
        attr_set = true;
    }

    // weights f32 -> fp16
    wconv_kernel<<<(CDIM * 3 * CDIM / 4 + 255) / 256, 256>>>(attn_w, wqkv, CDIM * 3 * CDIM / 4);
    wconv_kernel<<<(CDIM * CDIM / 4 + 255) / 256, 256>>>(proj_w, wproj, CDIM * CDIM / 4);
    wconv_kernel<<<(CDIM * 4 * CDIM / 4 + 255) / 256, 256>>>(fc_w, wfc, CDIM * 4 * CDIM / 4);
    wconv_kernel<<<(4 * CDIM * CDIM / 4 + 255) / 256, 256>>>(fc2_w, wfc2, 4 * CDIM * CDIM / 4);

    // 1) h = ln1(x)
    ln_kernel<<<MTOK, 256>>>(x, ln1_g, ln1_b, h);
    // 2) qkv = h @ attn_w + attn_b  (fp16 out)
    hgemm_kernel<0><<<dim3(2304 / 128, MTOK / 128), 128>>>(h, wqkv, attn_b, nullptr, nullptr, qkv, 2304, 768);
    // 3) y = causal MHA(qkv)  (fp16 out)
    attn_kernel<<<dim3(TSEQ / 64, NHEAD, BATCH), 256, sizeof(AttnSmem)>>>(qkv, y);
    // 4) x1 = x + y @ proj_w + proj_b  (f32 out)
    hgemm_kernel<1><<<dim3(768 / 128, MTOK / 128), 128>>>(y, wproj, proj_b, x, x1, nullptr, 768, 768);
    // 5) h = ln2(x1)
    ln_kernel<<<MTOK, 256>>>(x1, ln2_g, ln2_b, h);
    // 6) h2 = gelu(h @ fc_w + fc_b)  (fp16 out)
    hgemm_kernel<2><<<dim3(3072 / 128, MTOK / 128), 128>>>(h, wfc, fc_b, nullptr, nullptr, h2, 3072, 768);
    // 7) out = x1 + h2 @ fc2_w + fc2_b  (f32 out)
    hgemm_kernel<1><<<dim3(768 / 128, MTOK / 128), 128>>>(h2, wfc2, fc2_b, x1, out, nullptr, 768, 3072);
}

// round 7
// speedup vs baseline: 6.2589x; 1.0835x over previous
#include <cuda_runtime.h>
#include <cuda_fp16.h>
#include <math.h>
#include <mma.h>
#include <stdint.h>

using namespace nvcuda;

#define MTOK  16384
#define CDIM  768
#define TSEQ  1024
#define BATCH 16
#define NHEAD 8
#define HDIM  96

// ================= scratch (no allocation allowed) =================
__device__ __half g_h  [(size_t)MTOK * CDIM];
__device__ __half g_qkv[(size_t)MTOK * 3 * CDIM];
__device__ __half g_y  [(size_t)MTOK * CDIM];
__device__ float  g_x1 [(size_t)MTOK * CDIM];
__device__ __half g_h2 [(size_t)MTOK * 4 * CDIM];
__device__ __half g_wqkv[(size_t)CDIM * 3 * CDIM];
__device__ __half g_wproj[(size_t)CDIM * CDIM];
__device__ __half g_wfc [(size_t)CDIM * 4 * CDIM];
__device__ __half g_wfc2[(size_t)4 * CDIM * CDIM];

__device__ __forceinline__ float gelu_f(float x) {
    const float x3 = x * x * x;
    return 0.5f * x * (1.0f + tanhf(0.7978845608028654f * (x + 0.044715f * x3)));
}
__device__ __forceinline__ uint32_t smem_u32(const void* p) {
    return (uint32_t)__cvta_generic_to_shared(p);
}
__device__ __forceinline__ void cp16(uint32_t dst, const void* src) {
    asm volatile("cp.async.cg.shared.global [%0], [%1], 16;\n" :: "r"(dst), "l"(src));
}
#define CP_COMMIT() asm volatile("cp.async.commit_group;\n" ::: "memory")
#define CP_WAIT0()  asm volatile("cp.async.wait_group 0;\n" ::: "memory")
#define CP_WAIT1()  asm volatile("cp.async.wait_group 1;\n" ::: "memory")

// ================= weight f32 -> fp16 =================
__global__ __launch_bounds__(256) void wconv_kernel(
    const float* __restrict__ src, __half* __restrict__ dst, int n4)
{
    const int i = blockIdx.x * 256 + threadIdx.x;
    if (i < n4) {
        float4 v = ((const float4*)src)[i];
        __half2 a = __floats2half2_rn(v.x, v.y);
        __half2 b = __floats2half2_rn(v.z, v.w);
        *(uint2*)(dst + (size_t)i * 4) = make_uint2(*(uint32_t*)&a, *(uint32_t*)&b);
    }
}

// ================= layernorm (f32 in -> fp16 out) =================
__global__ __launch_bounds__(256) void ln_kernel(
    const float* __restrict__ x, const float* __restrict__ g,
    const float* __restrict__ b, __half* __restrict__ out)
{
    const int row = blockIdx.x;
    const int tid = threadIdx.x;
    const float* xr = x + (size_t)row * CDIM;
    float vals[3];
    float s = 0.f, s2 = 0.f;
#pragma unroll
    for (int j = 0; j < 3; j++) {
        float t = xr[tid + 256 * j];
        vals[j] = t; s += t; s2 += t * t;
    }
#pragma unroll
    for (int o = 16; o > 0; o >>= 1) {
        s  += __shfl_xor_sync(0xffffffffu, s,  o);
        s2 += __shfl_xor_sync(0xffffffffu, s2, o);
    }
    __shared__ float rs[8], rs2[8];
    const int wid = tid >> 5, lane = tid & 31;
    if (lane == 0) { rs[wid] = s; rs2[wid] = s2; }
    __syncthreads();
    s = 0.f; s2 = 0.f;
#pragma unroll
    for (int w = 0; w < 8; w++) { s += rs[w]; s2 += rs2[w]; }
    const float mu  = s * (1.0f / CDIM);
    const float var = s2 * (1.0f / CDIM) - mu * mu;
    const float rstd = rsqrtf(var + 1e-5f);
#pragma unroll
    for (int j = 0; j < 3; j++) {
        const int c = tid + 256 * j;
        out[(size_t)row * CDIM + c] = __float2half_rn((vals[j] - mu) * rstd * g[c] + b[c]);
    }
}

// ================= fp16 tensor-core GEMM, 3-stage pipeline =================
// block 128x128, BK=32, 128 threads (4 warps 2x2), warp tile 64x64.
#define AS_OFF 0
#define BS_OFF (3 * 128 * 40 * 2)
#define STG_OFF (BS_OFF + 3 * 32 * 136 * 2)
#define GEMM_SMEM (STG_OFF + 4 * 16 * 16 * 4)

// EPI: 0 = bias -> half ; 1 = bias+res(f32) -> f32 ; 2 = bias+gelu -> half
template <int EPI>
__global__ __launch_bounds__(128) void hgemm_kernel(
    const __half* __restrict__ A, const __half* __restrict__ B,
    const float* __restrict__ bias, const float* __restrict__ res,
    float* __restrict__ Cf, __half* __restrict__ Ch, int N, int K)
{
    extern __shared__ char dsm[];
    __half* Asb = (__half*)(dsm + AS_OFF);    // [3][128][40]
    __half* Bsb = (__half*)(dsm + BS_OFF);    // [3][32][136]
    float*  stg = (float*)(dsm + STG_OFF);    // [4][16][16]

    const int tid  = threadIdx.x;
    const int wid  = tid >> 5, lane = tid & 31;
    const int wm   = wid >> 1;
    const int wn   = wid & 1;
    const int bx   = blockIdx.x, by = blockIdx.y;

    wmma::fragment<wmma::accumulator, 16, 16, 16, float> c[4][4];
#pragma unroll
    for (int i = 0; i < 4; i++)
#pragma unroll
        for (int j = 0; j < 4; j++) wmma::fill_fragment(c[i][j], 0.0f);

    const __half* Agm = A + (size_t)(by * 128) * K;
    const __half* Bgm = B + bx * 128;
    const int nk = K >> 5;

    const int ar = tid >> 2, ak = (tid & 3) * 8;
    const int bk = tid >> 4, bc = (tid & 15) * 8;

    // copy one 32-k tile into stage s
    auto copy_tile = [&](int s, int kt) {
        const __half* An = Agm + kt * 32;
        const __half* Bn = Bgm + (size_t)(kt * 32) * N;
#pragma unroll
        for (int it = 0; it < 4; it++) {
            cp16(smem_u32(&Asb[((s * 128) + (ar + it * 32)) * 40 + ak]),
                 An + (size_t)(ar + it * 32) * K + ak);
            cp16(smem_u32(&Bsb[((s * 32) + (bk + it * 8)) * 136 + bc]),
                 Bn + (size_t)(bk + it * 8) * N + bc);
        }
    };

    copy_tile(0, 0); CP_COMMIT();
    copy_tile(1, 1); CP_COMMIT();

    int buf = 0, cslot = 2;
    for (int kt = 0; kt < nk; ++kt) {
        CP_WAIT1();           // stage kt complete (≤1 group pending = kt+1)
        __syncthreads();
        if (kt + 2 < nk) copy_tile(cslot, kt + 2);
        CP_COMMIT();          // always commit to keep group accounting uniform

#pragma unroll
        for (int ks = 0; ks < 2; ks++) {
            wmma::fragment<wmma::matrix_a, 16, 16, 16, __half, wmma::row_major> a[4];
            wmma::fragment<wmma::matrix_b, 16, 16, 16, __half, wmma::row_major> b[4];
#pragma unroll
            for (int mi = 0; mi < 4; mi++)
                wmma::load_matrix_sync(a[mi],
                    &Asb[((buf * 128) + (wm * 64 + mi * 16)) * 40 + ks * 16], 40);
#pragma unroll
            for (int nj = 0; nj < 4; nj++)
                wmma::load_matrix_sync(b[nj],
                    &Bsb[((buf * 32) + (ks * 16)) * 136 + wn * 64 + nj * 16], 136);
#pragma unroll
            for (int mi = 0; mi < 4; mi++)
#pragma unroll
                for (int nj = 0; nj < 4; nj++)
                    wmma::mma_sync(c[mi][nj], a[mi], b[nj], c[mi][nj]);
        }
        buf   = (buf   == 2) ? 0 : buf + 1;
        cslot = (cslot == 2) ? 0 : cslot + 1;
    }
    __syncthreads();

    // ---- epilogue via per-warp staging ----
    const int r  = lane >> 1;
    const int cs = (lane & 1) * 8;
    float* mystg = stg + wid * 256;
#pragma unroll
    for (int mi = 0; mi < 4; mi++) {
#pragma unroll
        for (int nj = 0; nj < 4; nj++) {
            wmma::store_matrix_sync(mystg, c[mi][nj], 16, wmma::mem_row_major);
            __syncwarp();
            const int row = by * 128 + wm * 64 + mi * 16 + r;
            const int col = bx * 128 + wn * 64 + nj * 16 + cs;
            const size_t base = (size_t)row * N + col;
            float4 b0 = *(const float4*)(bias + col);
            float4 b1 = *(const float4*)(bias + col + 4);
            float v[8];
#pragma unroll
            for (int u = 0; u < 8; u++) v[u] = mystg[r * 16 + cs + u];
            v[0] += b0.x; v[1] += b0.y; v[2] += b0.z; v[3] += b0.w;
            v[4] += b1.x; v[5] += b1.y; v[6] += b1.z; v[7] += b1.w;
            if (EPI == 1) {
                float4 r0 = *(const float4*)(res + base);
                float4 r1 = *(const float4*)(res + base + 4);
                v[0] += r0.x; v[1] += r0.y; v[2] += r0.z; v[3] += r0.w;
                v[4] += r1.x; v[5] += r1.y; v[6] += r1.z; v[7] += r1.w;
                *(float4*)(Cf + base)     = make_float4(v[0], v[1], v[2], v[3]);
                *(float4*)(Cf + base + 4) = make_float4(v[4], v[5], v[6], v[7]);
            } else {
                if (EPI == 2) {
#pragma unroll
                    for (int u = 0; u < 8; u++) v[u] = gelu_f(v[u]);
                }
                __half2 h0 = __floats2half2_rn(v[0], v[1]);
                __half2 h1 = __floats2half2_rn(v[2], v[3]);
                __half2 h2 = __floats2half2_rn(v[4], v[5]);
                __half2 h3 = __floats2half2_rn(v[6], v[7]);
                *(uint4*)(Ch + base) = make_uint4(
                    *(uint32_t*)&h0, *(uint32_t*)&h1, *(uint32_t*)&h2, *(uint32_t*)&h3);
            }
            __syncwarp();
        }
    }
}

// ================= fp16 tensor-core flash attention (causal) =================
// 64-query tile, 256 threads (8 warps: 4 m x 2 n), 64-key chunks.
// Q fragments persistent in registers; O-rescale fused into softmax pass.
struct AttnSmem {
    __half Qs[64][104];
    __half Ks[64][104];
    __half Vs[64][104];
    __half Ps[64][72];
    float  Ss[64][68];
    float  Os[64][100];
    float  m_s[64], l_s[64];
};

__global__ __launch_bounds__(256) void attn_kernel(
    const __half* __restrict__ qkv, __half* __restrict__ y)
{
    extern __shared__ char smem_raw[];
    AttnSmem& sm = *reinterpret_cast<AttnSmem*>(smem_raw);

    const int qt = blockIdx.x, h = blockIdx.y, b = blockIdx.z;
    const int tid = threadIdx.x;
    const int wid = tid >> 5;
    const int wm = wid >> 1;
    const int wn = wid & 1;
    const int q0 = qt * 64;
    const float scale = 0.10206207261596575f;

    // ---- load Q tile ----
#pragma unroll
    for (int i = 0; i < 3; i++) {
        const int idx = i * 256 + tid;
        const int row = idx / 12, c = (idx % 12) * 8;
        *(uint4*)&sm.Qs[row][c] =
            *(const uint4*)(qkv + (size_t)(b * TSEQ + q0 + row) * 2304 + h * 96 + c);
    }
#pragma unroll
    for (int i = 0; i < 25; i++)
        ((float*)sm.Os)[i * 256 + tid] = 0.f;
    if (tid < 64) { sm.m_s[tid] = -3e38f; sm.l_s[tid] = 0.f; }
    __syncthreads();

    // ---- persistent Q fragments ----
    wmma::fragment<wmma::matrix_a, 16, 16, 16, __half, wmma::row_major> qa[6];
#pragma unroll
    for (int ks = 0; ks < 6; ks++)
        wmma::load_matrix_sync(qa[ks], &sm.Qs[wm * 16][ks * 16], 104);

    for (int jc = 0; jc <= qt; ++jc) {
        const int kb = jc * 64;
        __syncthreads();   // prev PV done with Ks/Vs/Ps

#pragma unroll
        for (int i = 0; i < 3; i++) {
            const int idx = i * 256 + tid;
            const int row = idx / 12, c = (idx % 12) * 8;
            const __half* base = qkv + (size_t)(b * TSEQ + kb + row) * 2304 + h * 96 + c;
            *(uint4*)&sm.Ks[row][c] = *(const uint4*)(base + 768);
            *(uint4*)&sm.Vs[row][c] = *(const uint4*)(base + 1536);
        }
        __syncthreads();

        // ---- S = Q K^T ----
        {
            wmma::fragment<wmma::accumulator, 16, 16, 16, float> sc[2];
            wmma::fill_fragment(sc[0], 0.f);
            wmma::fill_fragment(sc[1], 0.f);
#pragma unroll
            for (int ks = 0; ks < 6; ks++) {
#pragma unroll
                for (int j = 0; j < 2; j++) {
                    wmma::fragment<wmma::matrix_b, 16, 16, 16, __half, wmma::col_major> bf;
                    wmma::load_matrix_sync(bf, &sm.Ks[wn * 32 + j * 16][ks * 16], 104);
                    wmma::mma_sync(sc[j], qa[ks], bf, sc[j]);
                }
            }
#pragma unroll
            for (int j = 0; j < 2; j++)
                wmma::store_matrix_sync(&sm.Ss[wm * 16][wn * 32 + j * 16], sc[j], 68, wmma::mem_row_major);
        }
        __syncthreads();

        // ---- online softmax + O rescale (4 threads/row) ----
        {
            const int row = tid >> 2;
            const int q4  = tid & 3;
            const int gq  = q0 + row;
            const bool diag = (jc == qt);
            const float m_old = sm.m_s[row];
            float sv[16];
            float mloc = -3e38f;
#pragma unroll
            for (int j = 0; j < 16; j++) {
                const int cc = q4 * 16 + j;
                float s = sm.Ss[row][cc] * scale;
                if (diag && (kb + cc > gq)) s = -3e38f;
                sv[j] = s;
                mloc = fmaxf(mloc, s);
            }
            mloc = fmaxf(mloc, __shfl_xor_sync(0xffffffffu, mloc, 1));
            mloc = fmaxf(mloc, __shfl_xor_sync(0xffffffffu, mloc, 2));
            const float m_new = fmaxf(m_old, mloc);
            float ls = 0.f;
#pragma unroll
            for (int j = 0; j < 16; j += 2) {
                const float p0 = __expf(sv[j]     - m_new);
                const float p1 = __expf(sv[j + 1] - m_new);
                ls += p0 + p1;
                *(__half2*)&sm.Ps[row][q4 * 16 + j] = __floats2half2_rn(p0, p1);
            }
            ls += __shfl_xor_sync(0xffffffffu, ls, 1);
            ls += __shfl_xor_sync(0xffffffffu, ls, 2);
            const float f = __expf(m_old - m_new);   // all 4 threads compute f
            if (q4 == 0) {
                sm.m_s[row] = m_new;
                sm.l_s[row] = sm.l_s[row] * f + ls;
            }
            // rescale this row's O slice (strided-4: conflict-free)
#pragma unroll
            for (int cc = 0; cc < 24; cc++)
                sm.Os[row][q4 + cc * 4] *= f;
        }
        __syncthreads();

        // ---- O += P V ----
        {
            wmma::fragment<wmma::accumulator, 16, 16, 16, float> oc[3];
#pragma unroll
            for (int j = 0; j < 3; j++)
                wmma::load_matrix_sync(oc[j], &sm.Os[wm * 16][wn * 48 + j * 16], 100, wmma::mem_row_major);
#pragma unroll
            for (int ks = 0; ks < 4; ks++) {
                wmma::fragment<wmma::matrix_a, 16, 16, 16, __half, wmma::row_major> pf;
                wmma::load_matrix_sync(pf, &sm.Ps[wm * 16][ks * 16], 72);
#pragma unroll
                for (int j = 0; j < 3; j++) {
                    wmma::fragment<wmma::matrix_b, 16, 16, 16, __half, wmma::row_major> vf;
                    wmma::load_matrix_sync(vf, &sm.Vs[ks * 16][wn * 48 + j * 16], 104);
                    wmma::mma_sync(oc[j], pf, vf, oc[j]);
                }
            }
#pragma unroll
            for (int j = 0; j < 3; j++)
                wmma::store_matrix_sync(&sm.Os[wm * 16][wn * 48 + j * 16], oc[j], 100, wmma::mem_row_major);
        }
    }
    __syncthreads();

    // ---- write y = O / l (fp16) ----
#pragma unroll
    for (int i = 0; i < 3; i++) {
        const int idx = i * 256 + tid;
        const int row = idx / 12, c = (idx % 12) * 8;
        const float inv = 1.0f / sm.l_s[row];
        const float* o = &sm.Os[row][c];
        __half2 h0 = __floats2half2_rn(o[0] * inv, o[1] * inv);
        __half2 h1 = __floats2half2_rn(o[2] * inv, o[3] * inv);
        __half2 h2 = __floats2half2_rn(o[4] * inv, o[5] * inv);
        __half2 h3 = __floats2half2_rn(o[6] * inv, o[7] * inv);
        *(uint4*)(y + (size_t)(b * TSEQ + q0 + row) * 768 + h * 96 + c) = make_uint4(
            *(uint32_t*)&h0, *(uint32_t*)&h1, *(uint32_t*)&h2, *(uint32_t*)&h3);
    }
}

// ================= launch =================
extern "C" void kernel_launch(void* const* d_in, const int* in_sizes, int n_in,
                              void* d_out, int out_size)
{
    const float* x      = (const float*)d_in[0];
    const float* ln1_g  = (const float*)d_in[1];
    const float* ln1_b  = (const float*)d_in[2];
    const float* attn_w = (const float*)d_in[3];
    const float* attn_b = (const float*)d_in[4];
    const float* proj_w = (const float*)d_in[5];
    const float* proj_b = (const float*)d_in[6];
    const float* ln2_g  = (const float*)d_in[7];
    const float* ln2_b  = (const float*)d_in[8];
    const float* fc_w   = (const float*)d_in[9];
    const float* fc_b   = (const float*)d_in[10];
    const float* fc2_w  = (const float*)d_in[11];
    const float* fc2_b  = (const float*)d_in[12];
    float* out = (float*)d_out;

    __half *h, *qkv, *y, *h2, *wqkv, *wproj, *wfc, *wfc2;
    float *x1;
    cudaGetSymbolAddress((void**)&h,    g_h);
    cudaGetSymbolAddress((void**)&qkv,  g_qkv);
    cudaGetSymbolAddress((void**)&y,    g_y);
    cudaGetSymbolAddress((void**)&x1,   g_x1);
    cudaGetSymbolAddress((void**)&h2,   g_h2);
    cudaGetSymbolAddress((void**)&wqkv, g_wqkv);
    cudaGetSymbolAddress((void**)&wproj,g_wproj);
    cudaGetSymbolAddress((void**)&wfc,  g_wfc);
    cudaGetSymbolAddress((void**)&wfc2, g_wfc2);

    static bool attr_set = false;
    if (!attr_set) {
        cudaFuncSetAttribute(attn_kernel, cudaFuncAttributeMaxDynamicSharedMemorySize,
                             (int)sizeof(AttnSmem));
        cudaFuncSetAttribute(hgemm_kernel<0>, cudaFuncAttributeMaxDynamicSharedMemorySize, GEMM_SMEM);
        cudaFuncSetAttribute(hgemm_kernel<1>, cudaFuncAttributeMaxDynamicSharedMemorySize, GEMM_SMEM);
        cudaFuncSetAttribute(hgemm_kernel<2>, cudaFuncAttributeMaxDynamicSharedMemorySize, GEMM_SMEM);
        attr_set = true;
    }

    wconv_kernel<<<(CDIM * 3 * CDIM / 4 + 255) / 256, 256>>>(attn_w, wqkv, CDIM * 3 * CDIM / 4);
    wconv_kernel<<<(CDIM * CDIM / 4 + 255) / 256, 256>>>(proj_w, wproj, CDIM * CDIM / 4);
    wconv_kernel<<<(CDIM * 4 * CDIM / 4 + 255) / 256, 256>>>(fc_w, wfc, CDIM * 4 * CDIM / 4);
    wconv_kernel<<<(4 * CDIM * CDIM / 4 + 255) / 256, 256>>>(fc2_w, wfc2, 4 * CDIM * CDIM / 4);

    ln_kernel<<<MTOK, 256>>>(x, ln1_g, ln1_b, h);
    hgemm_kernel<0><<<dim3(2304 / 128, MTOK / 128), 128, GEMM_SMEM>>>(
        h, wqkv, attn_b, nullptr, nullptr, qkv, 2304, 768);
    attn_kernel<<<dim3(TSEQ / 64, NHEAD, BATCH), 256, sizeof(AttnSmem)>>>(qkv, y);
    hgemm_kernel<1><<<dim3(768 / 128, MTOK / 128), 128, GEMM_SMEM>>>(
        y, wproj, proj_b, x, x1, nullptr, 768, 768);
    ln_kernel<<<MTOK, 256>>>(x1, ln2_g, ln2_b, h);
    hgemm_kernel<2><<<dim3(3072 / 128, MTOK / 128), 128, GEMM_SMEM>>>(
        h, wfc, fc_b, nullptr, nullptr, h2, 3072, 768);
    hgemm_kernel<1><<<dim3(768 / 128, MTOK / 128), 128, GEMM_SMEM>>>(
        h2, wfc2, fc2_b, x1, out, nullptr, 768, 3072);
}

// round 8
// speedup vs baseline: 6.4006x; 1.0226x over previous
#include <cuda_runtime.h>
#include <cuda_fp16.h>
#include <math.h>
#include <mma.h>
#include <stdint.h>

using namespace nvcuda;

#define MTOK  16384
#define CDIM  768
#define TSEQ  1024
#define BATCH 16
#define NHEAD 8
#define HDIM  96

// ================= scratch (no allocation allowed) =================
__device__ __half g_h  [(size_t)MTOK * CDIM];
__device__ __half g_qkv[(size_t)MTOK * 3 * CDIM];
__device__ __half g_y  [(size_t)MTOK * CDIM];
__device__ float  g_x1 [(size_t)MTOK * CDIM];
__device__ __half g_h2 [(size_t)MTOK * 4 * CDIM];
__device__ __half g_wqkv[(size_t)CDIM * 3 * CDIM];
__device__ __half g_wproj[(size_t)CDIM * CDIM];
__device__ __half g_wfc [(size_t)CDIM * 4 * CDIM];
__device__ __half g_wfc2[(size_t)4 * CDIM * CDIM];

__device__ __forceinline__ float gelu_f(float x) {
    const float x3 = x * x * x;
    return 0.5f * x * (1.0f + tanhf(0.7978845608028654f * (x + 0.044715f * x3)));
}
__device__ __forceinline__ uint32_t smem_u32(const void* p) {
    return (uint32_t)__cvta_generic_to_shared(p);
}
__device__ __forceinline__ void cp16(uint32_t dst, const void* src) {
    asm volatile("cp.async.cg.shared.global [%0], [%1], 16;\n" :: "r"(dst), "l"(src));
}
#define CP_COMMIT() asm volatile("cp.async.commit_group;\n" ::: "memory")
#define CP_WAIT1()  asm volatile("cp.async.wait_group 1;\n" ::: "memory")

// ================= weight f32 -> fp16 =================
__global__ __launch_bounds__(256) void wconv_kernel(
    const float* __restrict__ src, __half* __restrict__ dst, int n4)
{
    const int i = blockIdx.x * 256 + threadIdx.x;
    if (i < n4) {
        float4 v = ((const float4*)src)[i];
        __half2 a = __floats2half2_rn(v.x, v.y);
        __half2 b = __floats2half2_rn(v.z, v.w);
        *(uint2*)(dst + (size_t)i * 4) = make_uint2(*(uint32_t*)&a, *(uint32_t*)&b);
    }
}

// ================= layernorm (f32 in -> fp16 out) =================
__global__ __launch_bounds__(256) void ln_kernel(
    const float* __restrict__ x, const float* __restrict__ g,
    const float* __restrict__ b, __half* __restrict__ out)
{
    const int row = blockIdx.x;
    const int tid = threadIdx.x;
    const float* xr = x + (size_t)row * CDIM;
    float vals[3];
    float s = 0.f, s2 = 0.f;
#pragma unroll
    for (int j = 0; j < 3; j++) {
        float t = xr[tid + 256 * j];
        vals[j] = t; s += t; s2 += t * t;
    }
#pragma unroll
    for (int o = 16; o > 0; o >>= 1) {
        s  += __shfl_xor_sync(0xffffffffu, s,  o);
        s2 += __shfl_xor_sync(0xffffffffu, s2, o);
    }
    __shared__ float rs[8], rs2[8];
    const int wid = tid >> 5, lane = tid & 31;
    if (lane == 0) { rs[wid] = s; rs2[wid] = s2; }
    __syncthreads();
    s = 0.f; s2 = 0.f;
#pragma unroll
    for (int w = 0; w < 8; w++) { s += rs[w]; s2 += rs2[w]; }
    const float mu  = s * (1.0f / CDIM);
    const float var = s2 * (1.0f / CDIM) - mu * mu;
    const float rstd = rsqrtf(var + 1e-5f);
#pragma unroll
    for (int j = 0; j < 3; j++) {
        const int c = tid + 256 * j;
        out[(size_t)row * CDIM + c] = __float2half_rn((vals[j] - mu) * rstd * g[c] + b[c]);
    }
}

// ================= fp16 tensor-core GEMM, BK=64, 3-stage =================
#define AS_OFF 0
#define BS_OFF (3 * 128 * 72 * 2)             // 55296
#define STG_OFF (BS_OFF + 3 * 64 * 136 * 2)   // +52224
#define GEMM_SMEM (STG_OFF + 4 * 16 * 16 * 4) // +4096 = 111616

// EPI: 0 = bias -> half ; 1 = bias+res(f32) -> f32 ; 2 = bias+gelu -> half
template <int EPI>
__global__ __launch_bounds__(128) void hgemm_kernel(
    const __half* __restrict__ A, const __half* __restrict__ B,
    const float* __restrict__ bias, const float* __restrict__ res,
    float* __restrict__ Cf, __half* __restrict__ Ch, int N, int K)
{
    extern __shared__ char dsm[];
    __half* Asb = (__half*)(dsm + AS_OFF);    // [3][128][72]
    __half* Bsb = (__half*)(dsm + BS_OFF);    // [3][64][136]
    float*  stg = (float*)(dsm + STG_OFF);    // [4][16][16]

    const int tid  = threadIdx.x;
    const int wid  = tid >> 5, lane = tid & 31;
    const int wm   = wid >> 1;
    const int wn   = wid & 1;
    const int bx   = blockIdx.x, by = blockIdx.y;

    wmma::fragment<wmma::accumulator, 16, 16, 16, float> c[4][4];
#pragma unroll
    for (int i = 0; i < 4; i++)
#pragma unroll
        for (int j = 0; j < 4; j++) wmma::fill_fragment(c[i][j], 0.0f);

    const __half* Agm = A + (size_t)(by * 128) * K;
    const __half* Bgm = B + bx * 128;
    const int nk = K >> 6;

    const int arb = tid >> 3, ak = (tid & 7) * 8;   // A: 128r x 64k, 8 iters
    const int bkb = tid >> 4, bc = (tid & 15) * 8;  // B: 64k x 128n, 8 iters

    auto copy_tile = [&](int s, int kt) {
        const __half* An = Agm + kt * 64;
        const __half* Bn = Bgm + (size_t)(kt * 64) * N;
#pragma unroll
        for (int it = 0; it < 8; it++) {
            const int ar = arb + it * 16;
            const int bk = bkb + it * 8;
            cp16(smem_u32(&Asb[((s * 128) + ar) * 72 + ak]), An + (size_t)ar * K + ak);
            cp16(smem_u32(&Bsb[((s * 64) + bk) * 136 + bc]), Bn + (size_t)bk * N + bc);
        }
    };

    copy_tile(0, 0); CP_COMMIT();
    copy_tile(1, 1); CP_COMMIT();

    int buf = 0, cslot = 2;
    for (int kt = 0; kt < nk; ++kt) {
        CP_WAIT1();
        __syncthreads();
        if (kt + 2 < nk) copy_tile(cslot, kt + 2);
        CP_COMMIT();

#pragma unroll
        for (int ks = 0; ks < 4; ks++) {
            wmma::fragment<wmma::matrix_a, 16, 16, 16, __half, wmma::row_major> a[4];
            wmma::fragment<wmma::matrix_b, 16, 16, 16, __half, wmma::row_major> b[4];
#pragma unroll
            for (int mi = 0; mi < 4; mi++)
                wmma::load_matrix_sync(a[mi],
                    &Asb[((buf * 128) + (wm * 64 + mi * 16)) * 72 + ks * 16], 72);
#pragma unroll
            for (int nj = 0; nj < 4; nj++)
                wmma::load_matrix_sync(b[nj],
                    &Bsb[((buf * 64) + (ks * 16)) * 136 + wn * 64 + nj * 16], 136);
#pragma unroll
            for (int mi = 0; mi < 4; mi++)
#pragma unroll
                for (int nj = 0; nj < 4; nj++)
                    wmma::mma_sync(c[mi][nj], a[mi], b[nj], c[mi][nj]);
        }
        buf   = (buf   == 2) ? 0 : buf + 1;
        cslot = (cslot == 2) ? 0 : cslot + 1;
    }
    __syncthreads();

    // ---- epilogue via per-warp staging ----
    const int r  = lane >> 1;
    const int cs = (lane & 1) * 8;
    float* mystg = stg + wid * 256;
#pragma unroll
    for (int mi = 0; mi < 4; mi++) {
#pragma unroll
        for (int nj = 0; nj < 4; nj++) {
            wmma::store_matrix_sync(mystg, c[mi][nj], 16, wmma::mem_row_major);
            __syncwarp();
            const int row = by * 128 + wm * 64 + mi * 16 + r;
            const int col = bx * 128 + wn * 64 + nj * 16 + cs;
            const size_t base = (size_t)row * N + col;
            float4 b0 = *(const float4*)(bias + col);
            float4 b1 = *(const float4*)(bias + col + 4);
            float v[8];
#pragma unroll
            for (int u = 0; u < 8; u++) v[u] = mystg[r * 16 + cs + u];
            v[0] += b0.x; v[1] += b0.y; v[2] += b0.z; v[3] += b0.w;
            v[4] += b1.x; v[5] += b1.y; v[6] += b1.z; v[7] += b1.w;
            if (EPI == 1) {
                float4 r0 = *(const float4*)(res + base);
                float4 r1 = *(const float4*)(res + base + 4);
                v[0] += r0.x; v[1] += r0.y; v[2] += r0.z; v[3] += r0.w;
                v[4] += r1.x; v[5] += r1.y; v[6] += r1.z; v[7] += r1.w;
                *(float4*)(Cf + base)     = make_float4(v[0], v[1], v[2], v[3]);
                *(float4*)(Cf + base + 4) = make_float4(v[4], v[5], v[6], v[7]);
            } else {
                if (EPI == 2) {
#pragma unroll
                    for (int u = 0; u < 8; u++) v[u] = gelu_f(v[u]);
                }
                __half2 h0 = __floats2half2_rn(v[0], v[1]);
                __half2 h1 = __floats2half2_rn(v[2], v[3]);
                __half2 h2 = __floats2half2_rn(v[4], v[5]);
                __half2 h3 = __floats2half2_rn(v[6], v[7]);
                *(uint4*)(Ch + base) = make_uint4(
                    *(uint32_t*)&h0, *(uint32_t*)&h1, *(uint32_t*)&h2, *(uint32_t*)&h3);
            }
            __syncwarp();
        }
    }
}

// ================= fp16 flash attention, O in registers =================
// 64-query tile, 256 threads (8 warps: 4m x 2n), 64-key chunks.
struct AttnSmem {
    __half Qs[64][104];
    __half Ks[64][104];   // Ks+Vs reused as f32 [64][100] output staging
    __half Vs[64][104];
    __half Ps[64][72];
    float  Ss[64][68];
    float  fm[64][16];    // row-broadcast scale matrix (f, then 1/l)
    float  m_s[64], l_s[64];
};

__global__ __launch_bounds__(256) void attn_kernel(
    const __half* __restrict__ qkv, __half* __restrict__ y)
{
    extern __shared__ char smem_raw[];
    AttnSmem& sm = *reinterpret_cast<AttnSmem*>(smem_raw);

    const int qt = blockIdx.x, h = blockIdx.y, b = blockIdx.z;
    const int tid = threadIdx.x;
    const int wid = tid >> 5;
    const int wm = wid >> 1;
    const int wn = wid & 1;
    const int q0 = qt * 64;
    const float scale = 0.10206207261596575f;

    // ---- load Q tile ----
#pragma unroll
    for (int i = 0; i < 3; i++) {
        const int idx = i * 256 + tid;
        const int row = idx / 12, c = (idx % 12) * 8;
        *(uint4*)&sm.Qs[row][c] =
            *(const uint4*)(qkv + (size_t)(b * TSEQ + q0 + row) * 2304 + h * 96 + c);
    }
    if (tid < 64) { sm.m_s[tid] = -3e38f; sm.l_s[tid] = 0.f; }
    __syncthreads();

    // persistent Q fragments + register-resident O accumulators
    wmma::fragment<wmma::matrix_a, 16, 16, 16, __half, wmma::row_major> qa[6];
#pragma unroll
    for (int ks = 0; ks < 6; ks++)
        wmma::load_matrix_sync(qa[ks], &sm.Qs[wm * 16][ks * 16], 104);
    wmma::fragment<wmma::accumulator, 16, 16, 16, float> oc[3];
#pragma unroll
    for (int j = 0; j < 3; j++) wmma::fill_fragment(oc[j], 0.f);

    for (int jc = 0; jc <= qt; ++jc) {
        const int kb = jc * 64;
        __syncthreads();   // prev PV reads of Ks/Vs/Ps complete

#pragma unroll
        for (int i = 0; i < 3; i++) {
            const int idx = i * 256 + tid;
            const int row = idx / 12, c = (idx % 12) * 8;
            const __half* base = qkv + (size_t)(b * TSEQ + kb + row) * 2304 + h * 96 + c;
            *(uint4*)&sm.Ks[row][c] = *(const uint4*)(base + 768);
            *(uint4*)&sm.Vs[row][c] = *(const uint4*)(base + 1536);
        }
        __syncthreads();

        // ---- S = Q K^T ----
        {
            wmma::fragment<wmma::accumulator, 16, 16, 16, float> sc[2];
            wmma::fill_fragment(sc[0], 0.f);
            wmma::fill_fragment(sc[1], 0.f);
#pragma unroll
            for (int ks = 0; ks < 6; ks++) {
#pragma unroll
                for (int j = 0; j < 2; j++) {
                    wmma::fragment<wmma::matrix_b, 16, 16, 16, __half, wmma::col_major> bf;
                    wmma::load_matrix_sync(bf, &sm.Ks[wn * 32 + j * 16][ks * 16], 104);
                    wmma::mma_sync(sc[j], qa[ks], bf, sc[j]);
                }
            }
#pragma unroll
            for (int j = 0; j < 2; j++)
                wmma::store_matrix_sync(&sm.Ss[wm * 16][wn * 32 + j * 16], sc[j], 68, wmma::mem_row_major);
        }
        __syncthreads();

        // ---- online softmax (4 threads/row); f broadcast into fm ----
        {
            const int row = tid >> 2;
            const int q4  = tid & 3;
            const int gq  = q0 + row;
            const bool diag = (jc == qt);
            const float m_old = sm.m_s[row];
            float sv[16];
            float mloc = -3e38f;
#pragma unroll
            for (int j = 0; j < 16; j++) {
                const int cc = q4 * 16 + j;
                float s = sm.Ss[row][cc] * scale;
                if (diag && (kb + cc > gq)) s = -3e38f;
                sv[j] = s;
                mloc = fmaxf(mloc, s);
            }
            mloc = fmaxf(mloc, __shfl_xor_sync(0xffffffffu, mloc, 1));
            mloc = fmaxf(mloc, __shfl_xor_sync(0xffffffffu, mloc, 2));
            const float m_new = fmaxf(m_old, mloc);
            float ls = 0.f;
#pragma unroll
            for (int j = 0; j < 16; j += 2) {
                const float p0 = __expf(sv[j]     - m_new);
                const float p1 = __expf(sv[j + 1] - m_new);
                ls += p0 + p1;
                *(__half2*)&sm.Ps[row][q4 * 16 + j] = __floats2half2_rn(p0, p1);
            }
            ls += __shfl_xor_sync(0xffffffffu, ls, 1);
            ls += __shfl_xor_sync(0xffffffffu, ls, 2);
            const float f = __expf(m_old - m_new);
#pragma unroll
            for (int j = 0; j < 4; j++) sm.fm[row][q4 * 4 + j] = f;
            if (q4 == 0) {
                sm.m_s[row] = m_new;
                sm.l_s[row] = sm.l_s[row] * f + ls;
            }
        }
        __syncthreads();

        // ---- rescale O in registers (layout-agnostic via fragment mul) ----
        {
            wmma::fragment<wmma::accumulator, 16, 16, 16, float> F;
            wmma::load_matrix_sync(F, &sm.fm[wm * 16][0], 16, wmma::mem_row_major);
#pragma unroll
            for (int j = 0; j < 3; j++)
#pragma unroll
                for (int e = 0; e < F.num_elements; e++)
                    oc[j].x[e] *= F.x[e];
        }

        // ---- O += P V ----
#pragma unroll
        for (int ks = 0; ks < 4; ks++) {
            wmma::fragment<wmma::matrix_a, 16, 16, 16, __half, wmma::row_major> pf;
            wmma::load_matrix_sync(pf, &sm.Ps[wm * 16][ks * 16], 72);
#pragma unroll
            for (int j = 0; j < 3; j++) {
                wmma::fragment<wmma::matrix_b, 16, 16, 16, __half, wmma::row_major> vf;
                wmma::load_matrix_sync(vf, &sm.Vs[ks * 16][wn * 48 + j * 16], 104);
                wmma::mma_sync(oc[j], pf, vf, oc[j]);
            }
        }
    }
    __syncthreads();   // all warps done with Ks/Vs/fm

    // ---- final 1/l scaling via same fragment trick ----
    {
        const int row = tid >> 2;
        const int q4  = tid & 3;
        const float inv = 1.0f / sm.l_s[row];
#pragma unroll
        for (int j = 0; j < 4; j++) sm.fm[row][q4 * 4 + j] = inv;
    }
    __syncthreads();
    {
        wmma::fragment<wmma::accumulator, 16, 16, 16, float> F;
        wmma::load_matrix_sync(F, &sm.fm[wm * 16][0], 16, wmma::mem_row_major);
#pragma unroll
        for (int j = 0; j < 3; j++)
#pragma unroll
            for (int e = 0; e < F.num_elements; e++)
                oc[j].x[e] *= F.x[e];
    }

    // ---- stage O in (dead) K/V region, then write fp16 ----
    float* Ostage = (float*)sm.Ks;   // 64 x 100 f32 fits in Ks+Vs
#pragma unroll
    for (int j = 0; j < 3; j++)
        wmma::store_matrix_sync(&Ostage[(wm * 16) * 100 + wn * 48 + j * 16], oc[j], 100,
                                wmma::mem_row_major);
    __syncthreads();
#pragma unroll
    for (int i = 0; i < 6; i++) {
        const int idx = i * 256 + tid;
        const int row = idx / 24, c = idx % 24;
        const float* o = &Ostage[row * 100 + c * 4];
        __half2 h0 = __floats2half2_rn(o[0], o[1]);
        __half2 h1 = __floats2half2_rn(o[2], o[3]);
        *(uint2*)(y + (size_t)(b * TSEQ + q0 + row) * 768 + h * 96 + c * 4) =
            make_uint2(*(uint32_t*)&h0, *(uint32_t*)&h1);
    }
}

// ================= launch =================
extern "C" void kernel_launch(void* const* d_in, const int* in_sizes, int n_in,
                              void* d_out, int out_size)
{
    const float* x      = (const float*)d_in[0];
    const float* ln1_g  = (const float*)d_in[1];
    const float* ln1_b  = (const float*)d_in[2];
    const float* attn_w = (const float*)d_in[3];
    const float* attn_b = (const float*)d_in[4];
    const float* proj_w = (const float*)d_in[5];
    const float* proj_b = (const float*)d_in[6];
    const float* ln2_g  = (const float*)d_in[7];
    const float* ln2_b  = (const float*)d_in[8];
    const float* fc_w   = (const float*)d_in[9];
    const float* fc_b   = (const float*)d_in[10];
    const float* fc2_w  = (const float*)d_in[11];
    const float* fc2_b  = (const float*)d_in[12];
    float* out = (float*)d_out;

    __half *h, *qkv, *y, *h2, *wqkv, *wproj, *wfc, *wfc2;
    float *x1;
    cudaGetSymbolAddress((void**)&h,    g_h);
    cudaGetSymbolAddress((void**)&qkv,  g_qkv);
    cudaGetSymbolAddress((void**)&y,    g_y);
    cudaGetSymbolAddress((void**)&x1,   g_x1);
    cudaGetSymbolAddress((void**)&h2,   g_h2);
    cudaGetSymbolAddress((void**)&wqkv, g_wqkv);
    cudaGetSymbolAddress((void**)&wproj,g_wproj);
    cudaGetSymbolAddress((void**)&wfc,  g_wfc);
    cudaGetSymbolAddress((void**)&wfc2, g_wfc2);

    static bool attr_set = false;
    if (!attr_set) {
        cudaFuncSetAttribute(attn_kernel, cudaFuncAttributeMaxDynamicSharedMemorySize,
                             (int)sizeof(AttnSmem));
        cudaFuncSetAttribute(hgemm_kernel<0>, cudaFuncAttributeMaxDynamicSharedMemorySize, GEMM_SMEM);
        cudaFuncSetAttribute(hgemm_kernel<1>, cudaFuncAttributeMaxDynamicSharedMemorySize, GEMM_SMEM);
        cudaFuncSetAttribute(hgemm_kernel<2>, cudaFuncAttributeMaxDynamicSharedMemorySize, GEMM_SMEM);
        attr_set = true;
    }

    wconv_kernel<<<(CDIM * 3 * CDIM / 4 + 255) / 256, 256>>>(attn_w, wqkv, CDIM * 3 * CDIM / 4);
    wconv_kernel<<<(CDIM * CDIM / 4 + 255) / 256, 256>>>(proj_w, wproj, CDIM * CDIM / 4);
    wconv_kernel<<<(CDIM * 4 * CDIM / 4 + 255) / 256, 256>>>(fc_w, wfc, CDIM * 4 * CDIM / 4);
    wconv_kernel<<<(4 * CDIM * CDIM / 4 + 255) / 256, 256>>>(fc2_w, wfc2, 4 * CDIM * CDIM / 4);

    ln_kernel<<<MTOK, 256>>>(x, ln1_g, ln1_b, h);
    hgemm_kernel<0><<<dim3(2304 / 128, MTOK / 128), 128, GEMM_SMEM>>>(
        h, wqkv, attn_b, nullptr, nullptr, qkv, 2304, 768);
    attn_kernel<<<dim3(TSEQ / 64, NHEAD, BATCH), 256, sizeof(AttnSmem)>>>(qkv, y);
    hgemm_kernel<1><<<dim3(768 / 128, MTOK / 128), 128, GEMM_SMEM>>>(
        y, wproj, proj_b, x, x1, nullptr, 768, 768);
    ln_kernel<<<MTOK, 256>>>(x1, ln2_g, ln2_b, h);
    hgemm_kernel<2><<<dim3(3072 / 128, MTOK / 128), 128, GEMM_SMEM>>>(
        h, wfc, fc_b, nullptr, nullptr, h2, 3072, 768);
    hgemm_kernel<1><<<dim3(768 / 128, MTOK / 128), 128, GEMM_SMEM>>>(
        h2, wfc2, fc2_b, x1, out, nullptr, 768, 3072);
}